// round 14
// baseline (speedup 1.0000x reference)
#include <cuda_runtime.h>
#include <cuda_bf16.h>
#include <cuda_fp16.h>
#include <cstdint>

#define B_  2
#define S_  2048
#define D_  512
#define H_  8
#define DH_ 64
#define MM_ 2048          // MAX_SEQ (== S here)
#define BH_ (B_*H_)

// ---------------- scratch (static __device__, no allocation) ----------------
__device__ float g_Qp[B_*S_*D_];                 // 8 MB
__device__ float g_Kp[B_*S_*D_];                 // 8 MB
__device__ float g_Vp[B_*S_*D_];                 // 8 MB
__device__ float g_tmp[B_*S_*D_];                // 8 MB  (AV partial, k-half 0)
__device__ float g_tmp2[B_*S_*D_];               // 8 MB  (AV partial, k-half 1)
__device__ __half g_QE[(size_t)BH_*S_*MM_];      // 128 MB (Q @ E^T per b,h, fp16)

// ---------------- bf16 mma helper ----------------
__device__ __forceinline__ void mma_bf16(float c[4],
    uint32_t a0, uint32_t a1, uint32_t a2, uint32_t a3,
    uint32_t b0, uint32_t b1)
{
    asm volatile(
        "mma.sync.aligned.m16n8k16.row.col.f32.bf16.bf16.f32 "
        "{%0,%1,%2,%3}, {%4,%5,%6,%7}, {%8,%9}, {%0,%1,%2,%3};"
        : "+f"(c[0]), "+f"(c[1]), "+f"(c[2]), "+f"(c[3])
        : "r"(a0), "r"(a1), "r"(a2), "r"(a3), "r"(b0), "r"(b1));
}

// smem word layout: tile[rows][PADW] of uint32, word = bf16x2(k even, k odd).
// PADW % 32 == 4 -> fragment addr (g*PADW+tg) mod 32 = 4g+tg : conflict-free.
#define PADW 36
#define TILE_W (128 * PADW)                       // words per 128-row tile
#define TILE_W64 (64 * PADW)                      // words per 64-row tile
#define SMEM_TC (4 * TILE_W * 4)                  // 73728 B (A_hi,A_lo,B_hi,B_lo)
#define SMEM_AV ((2 * TILE_W + 2 * TILE_W64) * 4) // 55296 B
#define SMEM_QE (2 * TILE_W * 4)                  // 36864 B (hi-only A,B)

// gmem fp32 [128 x 64] k-contiguous tile -> smem bf16 hi/lo packed
__device__ __forceinline__ void ldcv_tile(
    uint32_t* __restrict__ hi, uint32_t* __restrict__ lo,
    const float* __restrict__ src, int row0, int ld, int tid)
{
#pragma unroll
    for (int l = 0; l < 8; l++) {
        int vv = tid + l * 256;
        int row = vv >> 4, c4 = (vv & 15) * 4;
        float4 a = *(const float4*)(src + (size_t)(row0 + row) * ld + c4);
        __nv_bfloat162 h0 = __floats2bfloat162_rn(a.x, a.y);   // .x = low = k even
        __nv_bfloat162 h1 = __floats2bfloat162_rn(a.z, a.w);
        float lx = a.x - __low2float(h0),  ly = a.y - __high2float(h0);
        float lz = a.z - __low2float(h1),  lw = a.w - __high2float(h1);
        __nv_bfloat162 l0 = __floats2bfloat162_rn(lx, ly);
        __nv_bfloat162 l1 = __floats2bfloat162_rn(lz, lw);
        int kw = row * PADW + (c4 >> 1);
        hi[kw]     = *(uint32_t*)&h0;  hi[kw + 1] = *(uint32_t*)&h1;
        lo[kw]     = *(uint32_t*)&l0;  lo[kw + 1] = *(uint32_t*)&l1;
    }
}

// hi-only variant (single-pass QE path)
__device__ __forceinline__ void ldcv_tile_hi(
    uint32_t* __restrict__ hi,
    const float* __restrict__ src, int row0, int ld, int tid)
{
#pragma unroll
    for (int l = 0; l < 8; l++) {
        int vv = tid + l * 256;
        int row = vv >> 4, c4 = (vv & 15) * 4;
        float4 a = *(const float4*)(src + (size_t)(row0 + row) * ld + c4);
        __nv_bfloat162 h0 = __floats2bfloat162_rn(a.x, a.y);
        __nv_bfloat162 h1 = __floats2bfloat162_rn(a.z, a.w);
        int kw = row * PADW + (c4 >> 1);
        hi[kw]     = *(uint32_t*)&h0;  hi[kw + 1] = *(uint32_t*)&h1;
    }
}

// same as ldcv_tile, but A = A1 + A2 (for the out-projection)
__device__ __forceinline__ void ldcv_tile_sum2(
    uint32_t* __restrict__ hi, uint32_t* __restrict__ lo,
    const float* __restrict__ s1, const float* __restrict__ s2,
    int row0, int ld, int tid)
{
#pragma unroll
    for (int l = 0; l < 8; l++) {
        int vv = tid + l * 256;
        int row = vv >> 4, c4 = (vv & 15) * 4;
        size_t off = (size_t)(row0 + row) * ld + c4;
        float4 a = *(const float4*)(s1 + off);
        float4 b = *(const float4*)(s2 + off);
        a.x += b.x; a.y += b.y; a.z += b.z; a.w += b.w;
        __nv_bfloat162 h0 = __floats2bfloat162_rn(a.x, a.y);
        __nv_bfloat162 h1 = __floats2bfloat162_rn(a.z, a.w);
        float lx = a.x - __low2float(h0),  ly = a.y - __high2float(h0);
        float lz = a.z - __low2float(h1),  lw = a.w - __high2float(h1);
        __nv_bfloat162 l0 = __floats2bfloat162_rn(lx, ly);
        __nv_bfloat162 l1 = __floats2bfloat162_rn(lz, lw);
        int kw = row * PADW + (c4 >> 1);
        hi[kw]     = *(uint32_t*)&h0;  hi[kw + 1] = *(uint32_t*)&h1;
        lo[kw]     = *(uint32_t*)&l0;  lo[kw + 1] = *(uint32_t*)&l1;
    }
}

// transpose-load: gmem fp32 chunk [64 k][N n] (k-major) -> Bs[n][kpair] hi/lo.
template<int N>
__device__ __forceinline__ void ldcv_tile_t(
    uint32_t* __restrict__ hi, uint32_t* __restrict__ lo,
    const float* __restrict__ src, int ld, int tid)
{
#pragma unroll
    for (int l = 0; l < (32 * (N / 4)) / 256; l++) {
        int idx = tid + l * 256;
        int nq = idx >> 5;            // 0..N/4-1
        int kp = idx & 31;            // 0..31
        int n = nq * 4;
        float4 r0 = *(const float4*)(src + (size_t)(kp * 2)     * ld + n);
        float4 r1 = *(const float4*)(src + (size_t)(kp * 2 + 1) * ld + n);
        float a0[4] = {r0.x, r0.y, r0.z, r0.w};
        float a1[4] = {r1.x, r1.y, r1.z, r1.w};
#pragma unroll
        for (int i = 0; i < 4; i++) {
            __nv_bfloat162 h = __floats2bfloat162_rn(a0[i], a1[i]);  // low = k even
            float lx = a0[i] - __low2float(h);
            float ly = a1[i] - __high2float(h);
            __nv_bfloat162 l2 = __floats2bfloat162_rn(lx, ly);
            hi[(n + i) * PADW + kp] = *(uint32_t*)&h;
            lo[(n + i) * PADW + kp] = *(uint32_t*)&l2;
        }
    }
}

// ============================================================================
// bf16x3 mainloop (3-pass): acc[4][4][4] += A[128x64]*Bs^T
// 8 warps: warp_m = wid&1 (64 rows), warp_n = wid>>1 (32 cols).
// ============================================================================
__device__ __forceinline__ void tc_nt_mainloop_bf16(
    const uint32_t* __restrict__ Ah, const uint32_t* __restrict__ Al,
    const uint32_t* __restrict__ Bh, const uint32_t* __restrict__ Bl,
    int warp_m, int warp_n, int g, int tg, float acc[4][4][4])
{
#pragma unroll
    for (int ks = 0; ks < 4; ks++) {
        const int base = ks * 8;
        uint32_t bh0[4], bh1[4], bl0[4], bl1[4];
#pragma unroll
        for (int nt = 0; nt < 4; nt++) {
            const int n0 = (warp_n * 32 + nt * 8 + g) * PADW + base + tg;
            bh0[nt] = Bh[n0]; bh1[nt] = Bh[n0 + 4];
            bl0[nt] = Bl[n0]; bl1[nt] = Bl[n0 + 4];
        }
#pragma unroll
        for (int mt = 0; mt < 4; mt++) {
            const int r0 = (warp_m * 64 + mt * 16 + g) * PADW + base + tg;
            const int r1 = r0 + 8 * PADW;
            uint32_t ah0 = Ah[r0], ah1 = Ah[r1], ah2 = Ah[r0 + 4], ah3 = Ah[r1 + 4];
            uint32_t al0 = Al[r0], al1 = Al[r1], al2 = Al[r0 + 4], al3 = Al[r1 + 4];
#pragma unroll
            for (int nt = 0; nt < 4; nt++) {
                mma_bf16(acc[mt][nt], ah0, ah1, ah2, ah3, bh0[nt], bh1[nt]);
                mma_bf16(acc[mt][nt], ah0, ah1, ah2, ah3, bl0[nt], bl1[nt]);
                mma_bf16(acc[mt][nt], al0, al1, al2, al3, bh0[nt], bh1[nt]);
            }
        }
    }
}

// single-pass (hi only) variant for the QE product
__device__ __forceinline__ void tc_nt_mainloop_bf16_hi(
    const uint32_t* __restrict__ Ah, const uint32_t* __restrict__ Bh,
    int warp_m, int warp_n, int g, int tg, float acc[4][4][4])
{
#pragma unroll
    for (int ks = 0; ks < 4; ks++) {
        const int base = ks * 8;
        uint32_t bh0[4], bh1[4];
#pragma unroll
        for (int nt = 0; nt < 4; nt++) {
            const int n0 = (warp_n * 32 + nt * 8 + g) * PADW + base + tg;
            bh0[nt] = Bh[n0]; bh1[nt] = Bh[n0 + 4];
        }
#pragma unroll
        for (int mt = 0; mt < 4; mt++) {
            const int r0 = (warp_m * 64 + mt * 16 + g) * PADW + base + tg;
            const int r1 = r0 + 8 * PADW;
            uint32_t ah0 = Ah[r0], ah1 = Ah[r1], ah2 = Ah[r0 + 4], ah3 = Ah[r1 + 4];
#pragma unroll
            for (int nt = 0; nt < 4; nt++)
                mma_bf16(acc[mt][nt], ah0, ah1, ah2, ah3, bh0[nt], bh1[nt]);
        }
    }
}

// AV variant (3-pass): BM=128 x BN=64.  warp_m = wid&3, warp_n = wid>>2.
__device__ __forceinline__ void tc_nt_mainloop_bf16_av(
    const uint32_t* __restrict__ Ah, const uint32_t* __restrict__ Al,
    const uint32_t* __restrict__ Bh, const uint32_t* __restrict__ Bl,
    int warp_m, int warp_n, int g, int tg, float acc[2][4][4])
{
#pragma unroll
    for (int ks = 0; ks < 4; ks++) {
        const int base = ks * 8;
        uint32_t bh0[4], bh1[4], bl0[4], bl1[4];
#pragma unroll
        for (int nt = 0; nt < 4; nt++) {
            const int n0 = (warp_n * 32 + nt * 8 + g) * PADW + base + tg;
            bh0[nt] = Bh[n0]; bh1[nt] = Bh[n0 + 4];
            bl0[nt] = Bl[n0]; bl1[nt] = Bl[n0 + 4];
        }
#pragma unroll
        for (int mt = 0; mt < 2; mt++) {
            const int r0 = (warp_m * 32 + mt * 16 + g) * PADW + base + tg;
            const int r1 = r0 + 8 * PADW;
            uint32_t ah0 = Ah[r0], ah1 = Ah[r1], ah2 = Ah[r0 + 4], ah3 = Ah[r1 + 4];
            uint32_t al0 = Al[r0], al1 = Al[r1], al2 = Al[r0 + 4], al3 = Al[r1 + 4];
#pragma unroll
            for (int nt = 0; nt < 4; nt++) {
                mma_bf16(acc[mt][nt], ah0, ah1, ah2, ah3, bh0[nt], bh1[nt]);
                mma_bf16(acc[mt][nt], ah0, ah1, ah2, ah3, bl0[nt], bl1[nt]);
                mma_bf16(acc[mt][nt], al0, al1, al2, al3, bh0[nt], bh1[nt]);
            }
        }
    }
}

// ============================================================================
// QE GEMM (NT, single-pass bf16), row-block persistent:
// one block per (bh, i-block); Q tile loaded+converted ONCE, loop over live
// E tiles (tj >= 15-ti).  Output fp16.
// ============================================================================
__global__ __launch_bounds__(256) void gemm_qe(
    const float* __restrict__ Qp, const float* __restrict__ E,
    __half* __restrict__ QE)
{
    const int ti = 15 - blockIdx.x;             // heavy rows (many tiles) first
    const int bm = ti * 128;
    const int bh = blockIdx.y;
    const float* A = Qp + (size_t)(bh >> 3) * S_ * D_ + (bh & 7) * DH_;
    const int tid = threadIdx.x;
    const int lane = tid & 31, wid = tid >> 5;
    const int warp_m = wid & 1, warp_n = wid >> 1;
    const int g = lane >> 2, tg = lane & 3;

    extern __shared__ uint32_t smw[];
    uint32_t* Ah = smw;
    uint32_t* Bh = smw + TILE_W;

    ldcv_tile_hi(Ah, A, bm, D_, tid);           // Q tile once

    __half* Cb = QE + (size_t)bh * S_ * MM_;
    for (int bn = (15 - ti) * 128; bn < MM_; bn += 128) {
        __syncthreads();                        // prior mainloop done with Bh
        ldcv_tile_hi(Bh, E, bn, DH_, tid);
        __syncthreads();

        float acc[4][4][4];
#pragma unroll
        for (int a = 0; a < 4; a++)
#pragma unroll
            for (int b = 0; b < 4; b++)
#pragma unroll
                for (int c = 0; c < 4; c++) acc[a][b][c] = 0.f;

        tc_nt_mainloop_bf16_hi(Ah, Bh, warp_m, warp_n, g, tg, acc);

#pragma unroll
        for (int mt = 0; mt < 4; mt++) {
            const int i0 = bm + warp_m * 64 + mt * 16 + g;
#pragma unroll
            for (int nt = 0; nt < 4; nt++) {
                const int j0 = bn + warp_n * 32 + nt * 8 + 2 * tg;
                *(__half2*)(Cb + (size_t)i0 * MM_ + j0) =
                    __floats2half2_rn(acc[mt][nt][0], acc[mt][nt][1]);
                *(__half2*)(Cb + (size_t)(i0 + 8) * MM_ + j0) =
                    __floats2half2_rn(acc[mt][nt][2], acc[mt][nt][3]);
            }
        }
    }
}

// ============================================================================
// Logits (NT, causal, bf16x3), row-block persistent:
// one block per (bh, i-block); Q tiles loaded+converted ONCE; loops over live
// K tiles, then zero-fills the dead (masked) tiles of its row-block.
// ============================================================================
__global__ __launch_bounds__(256) void logits_kernel(
    const float* __restrict__ Qp, const float* __restrict__ Kp,
    const __half* __restrict__ QE, float* __restrict__ attn)
{
    const int bm = (15 - blockIdx.x) * 128;     // heavy rows first
    const int bh = blockIdx.y;
    const float* A  = Qp + (size_t)(bh >> 3) * S_ * D_ + (bh & 7) * DH_;
    const float* Bt = Kp + (size_t)(bh >> 3) * S_ * D_ + (bh & 7) * DH_;
    const int tid = threadIdx.x;
    const int lane = tid & 31, wid = tid >> 5;
    const int warp_m = wid & 1, warp_n = wid >> 1;
    const int g = lane >> 2, tg = lane & 3;

    extern __shared__ uint32_t smw[];
    uint32_t* Ah = smw;
    uint32_t* Al = smw + TILE_W;
    uint32_t* Bh = smw + 2 * TILE_W;
    uint32_t* Bl = smw + 3 * TILE_W;

    ldcv_tile(Ah, Al, A, bm, D_, tid);          // Q tiles once

    const __half* QEr = QE + (size_t)bh * S_ * MM_;
    float* Cb = attn + (size_t)bh * S_ * S_;

    for (int bn = 0; bn <= bm; bn += 128) {
        __syncthreads();                        // prior mainloop done with Bh/Bl
        ldcv_tile(Bh, Bl, Bt, bn, D_, tid);
        __syncthreads();

        float acc[4][4][4];
#pragma unroll
        for (int a = 0; a < 4; a++)
#pragma unroll
            for (int b = 0; b < 4; b++)
#pragma unroll
                for (int c = 0; c < 4; c++) acc[a][b][c] = 0.f;

        tc_nt_mainloop_bf16(Ah, Al, Bh, Bl, warp_m, warp_n, g, tg, acc);

        if (bn < bm) {
            // fully unmasked tile: every (i,j) live
#pragma unroll
            for (int mt = 0; mt < 4; mt++) {
                const int ia = bm + warp_m * 64 + mt * 16 + g;
                const int ib = ia + 8;
#pragma unroll
                for (int nt = 0; nt < 4; nt++) {
                    const int j0 = bn + warp_n * 32 + nt * 8 + 2 * tg;
                    const int j1 = j0 + 1;
                    Cb[(size_t)ia * S_ + j0] =
                        (acc[mt][nt][0] + __half2float(QEr[(size_t)ia * MM_ + (j0 - ia + MM_ - 1)])) * 0.125f;
                    Cb[(size_t)ia * S_ + j1] =
                        (acc[mt][nt][1] + __half2float(QEr[(size_t)ia * MM_ + (j1 - ia + MM_ - 1)])) * 0.125f;
                    Cb[(size_t)ib * S_ + j0] =
                        (acc[mt][nt][2] + __half2float(QEr[(size_t)ib * MM_ + (j0 - ib + MM_ - 1)])) * 0.125f;
                    Cb[(size_t)ib * S_ + j1] =
                        (acc[mt][nt][3] + __half2float(QEr[(size_t)ib * MM_ + (j1 - ib + MM_ - 1)])) * 0.125f;
                }
            }
        } else {
            // diagonal tile: masked entries get exact 0 (QE load stays guarded)
#pragma unroll
            for (int mt = 0; mt < 4; mt++) {
                const int ia = bm + warp_m * 64 + mt * 16 + g;
                const int ib = ia + 8;
#pragma unroll
                for (int nt = 0; nt < 4; nt++) {
                    const int j0 = bn + warp_n * 32 + nt * 8 + 2 * tg;
                    const int j1 = j0 + 1;
                    if (j0 <= ia)
                        Cb[(size_t)ia * S_ + j0] =
                            (acc[mt][nt][0] + __half2float(QEr[(size_t)ia * MM_ + (j0 - ia + MM_ - 1)])) * 0.125f;
                    else Cb[(size_t)ia * S_ + j0] = 0.f;
                    if (j1 <= ia)
                        Cb[(size_t)ia * S_ + j1] =
                            (acc[mt][nt][1] + __half2float(QEr[(size_t)ia * MM_ + (j1 - ia + MM_ - 1)])) * 0.125f;
                    else Cb[(size_t)ia * S_ + j1] = 0.f;
                    if (j0 <= ib)
                        Cb[(size_t)ib * S_ + j0] =
                            (acc[mt][nt][2] + __half2float(QEr[(size_t)ib * MM_ + (j0 - ib + MM_ - 1)])) * 0.125f;
                    else Cb[(size_t)ib * S_ + j0] = 0.f;
                    if (j1 <= ib)
                        Cb[(size_t)ib * S_ + j1] =
                            (acc[mt][nt][3] + __half2float(QEr[(size_t)ib * MM_ + (j1 - ib + MM_ - 1)])) * 0.125f;
                    else Cb[(size_t)ib * S_ + j1] = 0.f;
                }
            }
        }
    }

    // dead tiles of this row-block: exact zeros (softmax no longer writes them)
    const float4 z = make_float4(0.f, 0.f, 0.f, 0.f);
    for (int bn = bm + 128; bn < S_; bn += 128) {
#pragma unroll
        for (int l = 0; l < 16; l++) {
            int idx = tid + l * 256;
            int row = idx >> 5, c4 = (idx & 31) * 4;
            *(float4*)(Cb + (size_t)(bm + row) * S_ + bn + c4) = z;
        }
    }
}

// ============================================================================
// Fused QKV projection (NN, bf16x3): K=512 in 8 chunks of 64.
// ============================================================================
__global__ __launch_bounds__(256) void proj_qkv(
    const float* __restrict__ q,  const float* __restrict__ k,
    const float* __restrict__ v,
    const float* __restrict__ Wq, const float* __restrict__ bq,
    const float* __restrict__ Wk, const float* __restrict__ bk,
    const float* __restrict__ Wv, const float* __restrict__ bv,
    float* __restrict__ Qp, float* __restrict__ Kp, float* __restrict__ Vp)
{
    const float *A, *W, *bias; float* C;
    if (blockIdx.z == 0)      { A = q; W = Wq; bias = bq; C = Qp; }
    else if (blockIdx.z == 1) { A = k; W = Wk; bias = bk; C = Kp; }
    else                      { A = v; W = Wv; bias = bv; C = Vp; }

    const int bm = blockIdx.y * 128;
    const int bn = blockIdx.x * 128;
    const int tid = threadIdx.x;
    const int lane = tid & 31, wid = tid >> 5;
    const int warp_m = wid & 1, warp_n = wid >> 1;
    const int g = lane >> 2, tg = lane & 3;

    extern __shared__ uint32_t smw[];
    uint32_t* Ah = smw;
    uint32_t* Al = smw + TILE_W;
    uint32_t* Bh = smw + 2 * TILE_W;
    uint32_t* Bl = smw + 3 * TILE_W;

    float acc[4][4][4];
#pragma unroll
    for (int a = 0; a < 4; a++)
#pragma unroll
        for (int b = 0; b < 4; b++)
#pragma unroll
            for (int c = 0; c < 4; c++) acc[a][b][c] = 0.f;

    for (int k0 = 0; k0 < D_; k0 += 64) {
        ldcv_tile(Ah, Al, A + k0, bm, D_, tid);
        ldcv_tile_t<128>(Bh, Bl, W + (size_t)k0 * D_ + bn, D_, tid);
        __syncthreads();
        tc_nt_mainloop_bf16(Ah, Al, Bh, Bl, warp_m, warp_n, g, tg, acc);
        __syncthreads();
    }

#pragma unroll
    for (int mt = 0; mt < 4; mt++) {
        const int i0 = bm + warp_m * 64 + mt * 16 + g;
#pragma unroll
        for (int nt = 0; nt < 4; nt++) {
            const int j0 = bn + warp_n * 32 + nt * 8 + 2 * tg;
            float b0 = bias[j0], b1 = bias[j0 + 1];
            *(float2*)(C + (size_t)i0 * D_ + j0) =
                make_float2(acc[mt][nt][0] + b0, acc[mt][nt][1] + b1);
            *(float2*)(C + (size_t)(i0 + 8) * D_ + j0) =
                make_float2(acc[mt][nt][2] + b0, acc[mt][nt][3] + b1);
        }
    }
}

// ============================================================================
// Out projection (NN, bf16x3) with summed A: C = (A1+A2) @ W + b.
// ============================================================================
__global__ __launch_bounds__(256) void sgemm_sum2_nn_bias(
    const float* __restrict__ A1, const float* __restrict__ A2,
    const float* __restrict__ W,  const float* __restrict__ bias,
    float* __restrict__ C)
{
    const int bm = blockIdx.y * 128;
    const int bn = blockIdx.x * 128;
    const int tid = threadIdx.x;
    const int lane = tid & 31, wid = tid >> 5;
    const int warp_m = wid & 1, warp_n = wid >> 1;
    const int g = lane >> 2, tg = lane & 3;

    extern __shared__ uint32_t smw[];
    uint32_t* Ah = smw;
    uint32_t* Al = smw + TILE_W;
    uint32_t* Bh = smw + 2 * TILE_W;
    uint32_t* Bl = smw + 3 * TILE_W;

    float acc[4][4][4];
#pragma unroll
    for (int a = 0; a < 4; a++)
#pragma unroll
        for (int b = 0; b < 4; b++)
#pragma unroll
            for (int c = 0; c < 4; c++) acc[a][b][c] = 0.f;

    for (int k0 = 0; k0 < D_; k0 += 64) {
        ldcv_tile_sum2(Ah, Al, A1 + k0, A2 + k0, bm, D_, tid);
        ldcv_tile_t<128>(Bh, Bl, W + (size_t)k0 * D_ + bn, D_, tid);
        __syncthreads();
        tc_nt_mainloop_bf16(Ah, Al, Bh, Bl, warp_m, warp_n, g, tg, acc);
        __syncthreads();
    }

#pragma unroll
    for (int mt = 0; mt < 4; mt++) {
        const int i0 = bm + warp_m * 64 + mt * 16 + g;
#pragma unroll
        for (int nt = 0; nt < 4; nt++) {
            const int j0 = bn + warp_n * 32 + nt * 8 + 2 * tg;
            float b0 = bias[j0], b1 = bias[j0 + 1];
            *(float2*)(C + (size_t)i0 * D_ + j0) =
                make_float2(acc[mt][nt][0] + b0, acc[mt][nt][1] + b1);
            *(float2*)(C + (size_t)(i0 + 8) * D_ + j0) =
                make_float2(acc[mt][nt][2] + b0, acc[mt][nt][3] + b1);
        }
    }
}

// ============================================================================
// Causal row softmax: stores ONLY j <= i (tail zeros now owned by logits).
// ============================================================================
__global__ void softmax_causal(float* __restrict__ attn)
{
    const int row = blockIdx.x;
    const int i   = row & (S_ - 1);
    float* p = attn + (size_t)row * S_;
    const int tid = threadIdx.x;

    float r[8];
    float mx = -1e30f;
#pragma unroll
    for (int l = 0; l < 8; l++) {
        int j = tid + (l << 8);
        r[l] = (j <= i) ? p[j] : -1e30f;
        mx = fmaxf(mx, r[l]);
    }
#pragma unroll
    for (int o = 16; o > 0; o >>= 1)
        mx = fmaxf(mx, __shfl_xor_sync(0xffffffffu, mx, o));
    __shared__ float smx[8];
    __shared__ float ssum[8];
    if ((tid & 31) == 0) smx[tid >> 5] = mx;
    __syncthreads();
#pragma unroll
    for (int w = 0; w < 8; w++) mx = fmaxf(mx, smx[w]);

    float sum = 0.f;
#pragma unroll
    for (int l = 0; l < 8; l++) {
        int j = tid + (l << 8);
        r[l] = (j <= i) ? __expf(r[l] - mx) : 0.f;
        sum += r[l];
    }
#pragma unroll
    for (int o = 16; o > 0; o >>= 1)
        sum += __shfl_xor_sync(0xffffffffu, sum, o);
    if ((tid & 31) == 0) ssum[tid >> 5] = sum;
    __syncthreads();
    float tot = 0.f;
#pragma unroll
    for (int w = 0; w < 8; w++) tot += ssum[w];
    const float inv = 1.f / tot;

#pragma unroll
    for (int l = 0; l < 8; l++) {
        int j = tid + (l << 8);
        if (j <= i) p[j] = r[l] * inv;
    }
}

// ============================================================================
// AV GEMM (NN, bf16x3): causal, split-K x2, heavy tiles first.
// ============================================================================
__global__ __launch_bounds__(256) void av_kernel(
    const float* __restrict__ attn, const float* __restrict__ Vp,
    float* __restrict__ O0, float* __restrict__ O1)
{
    const int bh = blockIdx.z;
    const int b = bh >> 3, h = bh & 7;
    const int bm = (15 - blockIdx.y) * 128;   // heavy tiles first
    const int kend = bm + 128;
    const int half = kend >> 1;               // multiple of 64
    const int kbeg = blockIdx.x * half;
    const int kfin = kbeg + half;
    float* Ot = blockIdx.x ? O1 : O0;

    const float* Ar = attn + (size_t)bh * S_ * S_;
    const float* Vr = Vp + (size_t)b * S_ * D_ + h * DH_;
    const int tid = threadIdx.x;
    const int lane = tid & 31, wid = tid >> 5;
    const int warp_m = wid & 3, warp_n = wid >> 2;
    const int g = lane >> 2, tg = lane & 3;

    extern __shared__ uint32_t smw[];
    uint32_t* Ah = smw;
    uint32_t* Al = smw + TILE_W;
    uint32_t* Bh = smw + 2 * TILE_W;
    uint32_t* Bl = smw + 2 * TILE_W + TILE_W64;

    float acc[2][4][4];
#pragma unroll
    for (int a = 0; a < 2; a++)
#pragma unroll
        for (int c = 0; c < 4; c++)
#pragma unroll
            for (int d = 0; d < 4; d++) acc[a][c][d] = 0.f;

    for (int k0 = kbeg; k0 < kfin; k0 += 64) {
        ldcv_tile(Ah, Al, Ar + k0, bm, S_, tid);
        ldcv_tile_t<64>(Bh, Bl, Vr + (size_t)k0 * D_, D_, tid);
        __syncthreads();
        tc_nt_mainloop_bf16_av(Ah, Al, Bh, Bl, warp_m, warp_n, g, tg, acc);
        __syncthreads();
    }

    float* Ob = Ot + (size_t)b * S_ * D_ + h * DH_;
#pragma unroll
    for (int mt = 0; mt < 2; mt++) {
        const int i0 = bm + warp_m * 32 + mt * 16 + g;
#pragma unroll
        for (int nt = 0; nt < 4; nt++) {
            const int j0 = warp_n * 32 + nt * 8 + 2 * tg;
            *(float2*)(Ob + (size_t)i0 * D_ + j0) =
                make_float2(acc[mt][nt][0], acc[mt][nt][1]);
            *(float2*)(Ob + (size_t)(i0 + 8) * D_ + j0) =
                make_float2(acc[mt][nt][2], acc[mt][nt][3]);
        }
    }
}

// ============================================================================
// launch
// ============================================================================
extern "C" void kernel_launch(void* const* d_in, const int* in_sizes, int n_in,
                              void* d_out, int out_size)
{
    const float* v  = (const float*)d_in[0];
    const float* k  = (const float*)d_in[1];
    const float* q  = (const float*)d_in[2];
    // d_in[3] = mask (implemented analytically)
    const float* Wq = (const float*)d_in[4];
    const float* bq = (const float*)d_in[5];
    const float* Wk = (const float*)d_in[6];
    const float* bk = (const float*)d_in[7];
    const float* Wv = (const float*)d_in[8];
    const float* bv = (const float*)d_in[9];
    const float* Wo = (const float*)d_in[10];
    const float* bo = (const float*)d_in[11];
    const float* E  = (const float*)d_in[12];

    float* out  = (float*)d_out;                       // (B,S,D)
    float* attn = (float*)d_out + (size_t)B_*S_*D_;    // (B,H,S,S)

    float *Qp, *Kp, *Vp, *Tmp, *Tmp2;
    __half* QE;
    cudaGetSymbolAddress((void**)&Qp,   g_Qp);
    cudaGetSymbolAddress((void**)&Kp,   g_Kp);
    cudaGetSymbolAddress((void**)&Vp,   g_Vp);
    cudaGetSymbolAddress((void**)&Tmp,  g_tmp);
    cudaGetSymbolAddress((void**)&Tmp2, g_tmp2);
    cudaGetSymbolAddress((void**)&QE,   g_QE);

    static int attr_done = 0;
    if (!attr_done) {
        cudaFuncSetAttribute(logits_kernel,      cudaFuncAttributeMaxDynamicSharedMemorySize, SMEM_TC);
        cudaFuncSetAttribute(proj_qkv,           cudaFuncAttributeMaxDynamicSharedMemorySize, SMEM_TC);
        cudaFuncSetAttribute(sgemm_sum2_nn_bias, cudaFuncAttributeMaxDynamicSharedMemorySize, SMEM_TC);
        cudaFuncSetAttribute(av_kernel,          cudaFuncAttributeMaxDynamicSharedMemorySize, SMEM_AV);
        attr_done = 1;
    }

    dim3 gProj(D_ / 128, (B_*S_) / 128, 3);  // (4, 32, 3)
    proj_qkv<<<gProj, 256, SMEM_TC>>>(q, k, v, Wq, bq, Wk, bk, Wv, bv, Qp, Kp, Vp);

    dim3 gQE(16, BH_);                       // row-block persistent, heavy first
    gemm_qe<<<gQE, 256, SMEM_QE>>>(Qp, E, QE);

    dim3 gLg(16, BH_);                       // row-block persistent, heavy first
    logits_kernel<<<gLg, 256, SMEM_TC>>>(Qp, Kp, QE, attn);

    softmax_causal<<<BH_ * S_, 256>>>(attn);

    dim3 gAV(2, S_ / 128, BH_);              // split-K x2
    av_kernel<<<gAV, 256, SMEM_AV>>>(attn, Vp, Tmp, Tmp2);

    dim3 gOut(D_ / 128, (B_*S_) / 128);
    sgemm_sum2_nn_bias<<<gOut, 256, SMEM_TC>>>(Tmp, Tmp2, Wo, bo, out);
}

// round 15
// speedup vs baseline: 1.2106x; 1.2106x over previous
#include <cuda_runtime.h>
#include <cuda_bf16.h>
#include <cuda_fp16.h>
#include <cstdint>

#define B_  2
#define S_  2048
#define D_  512
#define H_  8
#define DH_ 64
#define MM_ 2048          // MAX_SEQ (== S here)
#define BH_ (B_*H_)
#define DW_ (D_/2)        // packed words per row
#define DHW_ (DH_/2)      // packed words per head

// ---------------- scratch (static __device__, no allocation) ----------------
__device__ uint32_t g_Qh[B_*S_*DW_];             // 4 MB  Q hi (bf16x2 packed)
__device__ uint32_t g_Ql[B_*S_*DW_];             // 4 MB  Q lo
__device__ uint32_t g_Kh[B_*S_*DW_];             // 4 MB  K hi
__device__ uint32_t g_Kl[B_*S_*DW_];             // 4 MB  K lo
__device__ float    g_Vp[B_*S_*D_];              // 8 MB  V (fp32)
__device__ float    g_tmp[B_*S_*D_];             // 8 MB  (AV partial, k-half 0)
__device__ float    g_tmp2[B_*S_*D_];            // 8 MB  (AV partial, k-half 1)
__device__ __half   g_QE[(size_t)BH_*S_*MM_];    // 128 MB (Q @ E^T, fp16)

// ---------------- bf16 mma helper ----------------
__device__ __forceinline__ void mma_bf16(float c[4],
    uint32_t a0, uint32_t a1, uint32_t a2, uint32_t a3,
    uint32_t b0, uint32_t b1)
{
    asm volatile(
        "mma.sync.aligned.m16n8k16.row.col.f32.bf16.bf16.f32 "
        "{%0,%1,%2,%3}, {%4,%5,%6,%7}, {%8,%9}, {%0,%1,%2,%3};"
        : "+f"(c[0]), "+f"(c[1]), "+f"(c[2]), "+f"(c[3])
        : "r"(a0), "r"(a1), "r"(a2), "r"(a3), "r"(b0), "r"(b1));
}

// smem word layout: tile[rows][PADW] of uint32, word = bf16x2(k even, k odd).
#define PADW 36
#define TILE_W (128 * PADW)
#define TILE_W64 (64 * PADW)
#define SMEM_TC (4 * TILE_W * 4)                  // 73728 B
#define SMEM_AV ((2 * TILE_W + 2 * TILE_W64) * 4) // 55296 B
#define SMEM_QE (2 * TILE_W * 4)                  // 36864 B

// packed-word tile load: gmem uint32 [128 x 32 words] -> smem, NO conversion
__device__ __forceinline__ void ld_tile_pk(
    uint32_t* __restrict__ dst, const uint32_t* __restrict__ src,
    int row0, int ldw, int tid)
{
#pragma unroll
    for (int l = 0; l < 4; l++) {
        int vv = tid + l * 256;
        int row = vv >> 3, c = (vv & 7) * 4;
        uint4 a = *(const uint4*)(src + (size_t)(row0 + row) * ldw + c);
        *(uint4*)&dst[row * PADW + c] = a;
    }
}

// gmem fp32 [128 x 64] k-contiguous tile -> smem bf16 hi/lo packed (AV path)
__device__ __forceinline__ void ldcv_tile(
    uint32_t* __restrict__ hi, uint32_t* __restrict__ lo,
    const float* __restrict__ src, int row0, int ld, int tid)
{
#pragma unroll
    for (int l = 0; l < 8; l++) {
        int vv = tid + l * 256;
        int row = vv >> 4, c4 = (vv & 15) * 4;
        float4 a = *(const float4*)(src + (size_t)(row0 + row) * ld + c4);
        __nv_bfloat162 h0 = __floats2bfloat162_rn(a.x, a.y);   // .x = low = k even
        __nv_bfloat162 h1 = __floats2bfloat162_rn(a.z, a.w);
        float lx = a.x - __low2float(h0),  ly = a.y - __high2float(h0);
        float lz = a.z - __low2float(h1),  lw = a.w - __high2float(h1);
        __nv_bfloat162 l0 = __floats2bfloat162_rn(lx, ly);
        __nv_bfloat162 l1 = __floats2bfloat162_rn(lz, lw);
        int kw = row * PADW + (c4 >> 1);
        hi[kw]     = *(uint32_t*)&h0;  hi[kw + 1] = *(uint32_t*)&h1;
        lo[kw]     = *(uint32_t*)&l0;  lo[kw + 1] = *(uint32_t*)&l1;
    }
}

// hi-only variant (QE E-side: E input is fp32)
__device__ __forceinline__ void ldcv_tile_hi(
    uint32_t* __restrict__ hi,
    const float* __restrict__ src, int row0, int ld, int tid)
{
#pragma unroll
    for (int l = 0; l < 8; l++) {
        int vv = tid + l * 256;
        int row = vv >> 4, c4 = (vv & 15) * 4;
        float4 a = *(const float4*)(src + (size_t)(row0 + row) * ld + c4);
        __nv_bfloat162 h0 = __floats2bfloat162_rn(a.x, a.y);
        __nv_bfloat162 h1 = __floats2bfloat162_rn(a.z, a.w);
        int kw = row * PADW + (c4 >> 1);
        hi[kw]     = *(uint32_t*)&h0;  hi[kw + 1] = *(uint32_t*)&h1;
    }
}

// A = A1 + A2 (out-projection)
__device__ __forceinline__ void ldcv_tile_sum2(
    uint32_t* __restrict__ hi, uint32_t* __restrict__ lo,
    const float* __restrict__ s1, const float* __restrict__ s2,
    int row0, int ld, int tid)
{
#pragma unroll
    for (int l = 0; l < 8; l++) {
        int vv = tid + l * 256;
        int row = vv >> 4, c4 = (vv & 15) * 4;
        size_t off = (size_t)(row0 + row) * ld + c4;
        float4 a = *(const float4*)(s1 + off);
        float4 b = *(const float4*)(s2 + off);
        a.x += b.x; a.y += b.y; a.z += b.z; a.w += b.w;
        __nv_bfloat162 h0 = __floats2bfloat162_rn(a.x, a.y);
        __nv_bfloat162 h1 = __floats2bfloat162_rn(a.z, a.w);
        float lx = a.x - __low2float(h0),  ly = a.y - __high2float(h0);
        float lz = a.z - __low2float(h1),  lw = a.w - __high2float(h1);
        __nv_bfloat162 l0 = __floats2bfloat162_rn(lx, ly);
        __nv_bfloat162 l1 = __floats2bfloat162_rn(lz, lw);
        int kw = row * PADW + (c4 >> 1);
        hi[kw]     = *(uint32_t*)&h0;  hi[kw + 1] = *(uint32_t*)&h1;
        lo[kw]     = *(uint32_t*)&l0;  lo[kw + 1] = *(uint32_t*)&l1;
    }
}

// transpose-load: gmem fp32 chunk [64 k][N n] (k-major) -> Bs[n][kpair] hi/lo.
template<int N>
__device__ __forceinline__ void ldcv_tile_t(
    uint32_t* __restrict__ hi, uint32_t* __restrict__ lo,
    const float* __restrict__ src, int ld, int tid)
{
#pragma unroll
    for (int l = 0; l < (32 * (N / 4)) / 256; l++) {
        int idx = tid + l * 256;
        int nq = idx >> 5;
        int kp = idx & 31;
        int n = nq * 4;
        float4 r0 = *(const float4*)(src + (size_t)(kp * 2)     * ld + n);
        float4 r1 = *(const float4*)(src + (size_t)(kp * 2 + 1) * ld + n);
        float a0[4] = {r0.x, r0.y, r0.z, r0.w};
        float a1[4] = {r1.x, r1.y, r1.z, r1.w};
#pragma unroll
        for (int i = 0; i < 4; i++) {
            __nv_bfloat162 h = __floats2bfloat162_rn(a0[i], a1[i]);
            float lx = a0[i] - __low2float(h);
            float ly = a1[i] - __high2float(h);
            __nv_bfloat162 l2 = __floats2bfloat162_rn(lx, ly);
            hi[(n + i) * PADW + kp] = *(uint32_t*)&h;
            lo[(n + i) * PADW + kp] = *(uint32_t*)&l2;
        }
    }
}

// ============================================================================
// bf16x3 mainloop (3-pass)
// ============================================================================
__device__ __forceinline__ void tc_nt_mainloop_bf16(
    const uint32_t* __restrict__ Ah, const uint32_t* __restrict__ Al,
    const uint32_t* __restrict__ Bh, const uint32_t* __restrict__ Bl,
    int warp_m, int warp_n, int g, int tg, float acc[4][4][4])
{
#pragma unroll
    for (int ks = 0; ks < 4; ks++) {
        const int base = ks * 8;
        uint32_t bh0[4], bh1[4], bl0[4], bl1[4];
#pragma unroll
        for (int nt = 0; nt < 4; nt++) {
            const int n0 = (warp_n * 32 + nt * 8 + g) * PADW + base + tg;
            bh0[nt] = Bh[n0]; bh1[nt] = Bh[n0 + 4];
            bl0[nt] = Bl[n0]; bl1[nt] = Bl[n0 + 4];
        }
#pragma unroll
        for (int mt = 0; mt < 4; mt++) {
            const int r0 = (warp_m * 64 + mt * 16 + g) * PADW + base + tg;
            const int r1 = r0 + 8 * PADW;
            uint32_t ah0 = Ah[r0], ah1 = Ah[r1], ah2 = Ah[r0 + 4], ah3 = Ah[r1 + 4];
            uint32_t al0 = Al[r0], al1 = Al[r1], al2 = Al[r0 + 4], al3 = Al[r1 + 4];
#pragma unroll
            for (int nt = 0; nt < 4; nt++) {
                mma_bf16(acc[mt][nt], ah0, ah1, ah2, ah3, bh0[nt], bh1[nt]);
                mma_bf16(acc[mt][nt], ah0, ah1, ah2, ah3, bl0[nt], bl1[nt]);
                mma_bf16(acc[mt][nt], al0, al1, al2, al3, bh0[nt], bh1[nt]);
            }
        }
    }
}

// single-pass (hi only)
__device__ __forceinline__ void tc_nt_mainloop_bf16_hi(
    const uint32_t* __restrict__ Ah, const uint32_t* __restrict__ Bh,
    int warp_m, int warp_n, int g, int tg, float acc[4][4][4])
{
#pragma unroll
    for (int ks = 0; ks < 4; ks++) {
        const int base = ks * 8;
        uint32_t bh0[4], bh1[4];
#pragma unroll
        for (int nt = 0; nt < 4; nt++) {
            const int n0 = (warp_n * 32 + nt * 8 + g) * PADW + base + tg;
            bh0[nt] = Bh[n0]; bh1[nt] = Bh[n0 + 4];
        }
#pragma unroll
        for (int mt = 0; mt < 4; mt++) {
            const int r0 = (warp_m * 64 + mt * 16 + g) * PADW + base + tg;
            const int r1 = r0 + 8 * PADW;
            uint32_t ah0 = Ah[r0], ah1 = Ah[r1], ah2 = Ah[r0 + 4], ah3 = Ah[r1 + 4];
#pragma unroll
            for (int nt = 0; nt < 4; nt++)
                mma_bf16(acc[mt][nt], ah0, ah1, ah2, ah3, bh0[nt], bh1[nt]);
        }
    }
}

// AV variant: BM=128 x BN=64.
__device__ __forceinline__ void tc_nt_mainloop_bf16_av(
    const uint32_t* __restrict__ Ah, const uint32_t* __restrict__ Al,
    const uint32_t* __restrict__ Bh, const uint32_t* __restrict__ Bl,
    int warp_m, int warp_n, int g, int tg, float acc[2][4][4])
{
#pragma unroll
    for (int ks = 0; ks < 4; ks++) {
        const int base = ks * 8;
        uint32_t bh0[4], bh1[4], bl0[4], bl1[4];
#pragma unroll
        for (int nt = 0; nt < 4; nt++) {
            const int n0 = (warp_n * 32 + nt * 8 + g) * PADW + base + tg;
            bh0[nt] = Bh[n0]; bh1[nt] = Bh[n0 + 4];
            bl0[nt] = Bl[n0]; bl1[nt] = Bl[n0 + 4];
        }
#pragma unroll
        for (int mt = 0; mt < 2; mt++) {
            const int r0 = (warp_m * 32 + mt * 16 + g) * PADW + base + tg;
            const int r1 = r0 + 8 * PADW;
            uint32_t ah0 = Ah[r0], ah1 = Ah[r1], ah2 = Ah[r0 + 4], ah3 = Ah[r1 + 4];
            uint32_t al0 = Al[r0], al1 = Al[r1], al2 = Al[r0 + 4], al3 = Al[r1 + 4];
#pragma unroll
            for (int nt = 0; nt < 4; nt++) {
                mma_bf16(acc[mt][nt], ah0, ah1, ah2, ah3, bh0[nt], bh1[nt]);
                mma_bf16(acc[mt][nt], ah0, ah1, ah2, ah3, bl0[nt], bl1[nt]);
                mma_bf16(acc[mt][nt], al0, al1, al2, al3, bh0[nt], bh1[nt]);
            }
        }
    }
}

// ============================================================================
// QE GEMM (NT, single-pass bf16), per-tile grid (R13), Q from packed hi plane.
// ============================================================================
__global__ __launch_bounds__(256) void gemm_qe(
    const uint32_t* __restrict__ Qh, const float* __restrict__ E,
    __half* __restrict__ QE)
{
    if (blockIdx.x + blockIdx.y < 15) return;   // never-read tiles
    const int bh = blockIdx.z;
    const uint32_t* A = Qh + (size_t)(bh >> 3) * S_ * DW_ + (bh & 7) * DHW_;
    const int bm = blockIdx.y * 128;
    const int bn = blockIdx.x * 128;
    const int tid = threadIdx.x;
    const int lane = tid & 31, wid = tid >> 5;
    const int warp_m = wid & 1, warp_n = wid >> 1;
    const int g = lane >> 2, tg = lane & 3;

    extern __shared__ uint32_t smw[];
    uint32_t* Ah = smw;
    uint32_t* Bh = smw + TILE_W;

    ld_tile_pk(Ah, A, bm, DW_, tid);            // direct copy, no cvt
    ldcv_tile_hi(Bh, E, bn, DH_, tid);
    __syncthreads();

    float acc[4][4][4];
#pragma unroll
    for (int a = 0; a < 4; a++)
#pragma unroll
        for (int b = 0; b < 4; b++)
#pragma unroll
            for (int c = 0; c < 4; c++) acc[a][b][c] = 0.f;

    tc_nt_mainloop_bf16_hi(Ah, Bh, warp_m, warp_n, g, tg, acc);

    __half* Cb = QE + (size_t)bh * S_ * MM_;
#pragma unroll
    for (int mt = 0; mt < 4; mt++) {
        const int i0 = bm + warp_m * 64 + mt * 16 + g;
#pragma unroll
        for (int nt = 0; nt < 4; nt++) {
            const int j0 = bn + warp_n * 32 + nt * 8 + 2 * tg;
            *(__half2*)(Cb + (size_t)i0 * MM_ + j0) =
                __floats2half2_rn(acc[mt][nt][0], acc[mt][nt][1]);
            *(__half2*)(Cb + (size_t)(i0 + 8) * MM_ + j0) =
                __floats2half2_rn(acc[mt][nt][2], acc[mt][nt][3]);
        }
    }
}

// ============================================================================
// Logits (NT, causal, bf16x3), per-tile grid (R13), Q/K from packed planes.
// ============================================================================
__global__ __launch_bounds__(256) void logits_kernel(
    const uint32_t* __restrict__ Qh, const uint32_t* __restrict__ Ql,
    const uint32_t* __restrict__ Kh, const uint32_t* __restrict__ Kl,
    const __half* __restrict__ QE, float* __restrict__ attn)
{
    const int bm = blockIdx.y * 128;
    const int bn = blockIdx.x * 128;
    if (bn > bm + 127) return;
    const int bh = blockIdx.z;
    const size_t hoff = (size_t)(bh >> 3) * S_ * DW_ + (bh & 7) * DHW_;
    const int tid = threadIdx.x;
    const int lane = tid & 31, wid = tid >> 5;
    const int warp_m = wid & 1, warp_n = wid >> 1;
    const int g = lane >> 2, tg = lane & 3;

    extern __shared__ uint32_t smw[];
    uint32_t* Ah = smw;
    uint32_t* Al = smw + TILE_W;
    uint32_t* Bh = smw + 2 * TILE_W;
    uint32_t* Bl = smw + 3 * TILE_W;

    ld_tile_pk(Ah, Qh + hoff, bm, DW_, tid);
    ld_tile_pk(Al, Ql + hoff, bm, DW_, tid);
    ld_tile_pk(Bh, Kh + hoff, bn, DW_, tid);
    ld_tile_pk(Bl, Kl + hoff, bn, DW_, tid);
    __syncthreads();

    float acc[4][4][4];
#pragma unroll
    for (int a = 0; a < 4; a++)
#pragma unroll
        for (int b = 0; b < 4; b++)
#pragma unroll
            for (int c = 0; c < 4; c++) acc[a][b][c] = 0.f;

    tc_nt_mainloop_bf16(Ah, Al, Bh, Bl, warp_m, warp_n, g, tg, acc);

    const __half* QEr = QE + (size_t)bh * S_ * MM_;
    float* Cb = attn + (size_t)bh * S_ * S_;
#pragma unroll
    for (int mt = 0; mt < 4; mt++) {
        const int ia = bm + warp_m * 64 + mt * 16 + g;
        const int ib = ia + 8;
#pragma unroll
        for (int nt = 0; nt < 4; nt++) {
            const int j0 = bn + warp_n * 32 + nt * 8 + 2 * tg;
            const int j1 = j0 + 1;
            if (j0 <= ia)
                Cb[(size_t)ia * S_ + j0] =
                    (acc[mt][nt][0] + __half2float(QEr[(size_t)ia * MM_ + (j0 - ia + MM_ - 1)])) * 0.125f;
            if (j1 <= ia)
                Cb[(size_t)ia * S_ + j1] =
                    (acc[mt][nt][1] + __half2float(QEr[(size_t)ia * MM_ + (j1 - ia + MM_ - 1)])) * 0.125f;
            if (j0 <= ib)
                Cb[(size_t)ib * S_ + j0] =
                    (acc[mt][nt][2] + __half2float(QEr[(size_t)ib * MM_ + (j0 - ib + MM_ - 1)])) * 0.125f;
            if (j1 <= ib)
                Cb[(size_t)ib * S_ + j1] =
                    (acc[mt][nt][3] + __half2float(QEr[(size_t)ib * MM_ + (j1 - ib + MM_ - 1)])) * 0.125f;
        }
    }
}

// ============================================================================
// Fused QKV projection (NN, bf16x3): Q,K written as packed bf16 hi/lo planes;
// V written fp32.  Split at the producer — bit-identical to load-time split.
// ============================================================================
__global__ __launch_bounds__(256) void proj_qkv(
    const float* __restrict__ q,  const float* __restrict__ k,
    const float* __restrict__ v,
    const float* __restrict__ Wq, const float* __restrict__ bq,
    const float* __restrict__ Wk, const float* __restrict__ bk,
    const float* __restrict__ Wv, const float* __restrict__ bv,
    uint32_t* __restrict__ Qh, uint32_t* __restrict__ Ql,
    uint32_t* __restrict__ Kh, uint32_t* __restrict__ Kl,
    float* __restrict__ Vp)
{
    const float *A, *W, *bias;
    uint32_t *Ch = nullptr, *Cl = nullptr;
    if (blockIdx.z == 0)      { A = q; W = Wq; bias = bq; Ch = Qh; Cl = Ql; }
    else if (blockIdx.z == 1) { A = k; W = Wk; bias = bk; Ch = Kh; Cl = Kl; }
    else                      { A = v; W = Wv; bias = bv; }

    const int bm = blockIdx.y * 128;
    const int bn = blockIdx.x * 128;
    const int tid = threadIdx.x;
    const int lane = tid & 31, wid = tid >> 5;
    const int warp_m = wid & 1, warp_n = wid >> 1;
    const int g = lane >> 2, tg = lane & 3;

    extern __shared__ uint32_t smw[];
    uint32_t* Ah = smw;
    uint32_t* Al = smw + TILE_W;
    uint32_t* Bh = smw + 2 * TILE_W;
    uint32_t* Bl = smw + 3 * TILE_W;

    float acc[4][4][4];
#pragma unroll
    for (int a = 0; a < 4; a++)
#pragma unroll
        for (int b = 0; b < 4; b++)
#pragma unroll
            for (int c = 0; c < 4; c++) acc[a][b][c] = 0.f;

    for (int k0 = 0; k0 < D_; k0 += 64) {
        ldcv_tile(Ah, Al, A + k0, bm, D_, tid);
        ldcv_tile_t<128>(Bh, Bl, W + (size_t)k0 * D_ + bn, D_, tid);
        __syncthreads();
        tc_nt_mainloop_bf16(Ah, Al, Bh, Bl, warp_m, warp_n, g, tg, acc);
        __syncthreads();
    }

#pragma unroll
    for (int mt = 0; mt < 4; mt++) {
        const int i0 = bm + warp_m * 64 + mt * 16 + g;
#pragma unroll
        for (int nt = 0; nt < 4; nt++) {
            const int j0 = bn + warp_n * 32 + nt * 8 + 2 * tg;
            float b0 = bias[j0], b1 = bias[j0 + 1];
            float x0 = acc[mt][nt][0] + b0, x1 = acc[mt][nt][1] + b1;
            float y0 = acc[mt][nt][2] + b0, y1 = acc[mt][nt][3] + b1;
            if (blockIdx.z == 2) {
                *(float2*)(Vp + (size_t)i0 * D_ + j0)       = make_float2(x0, x1);
                *(float2*)(Vp + (size_t)(i0 + 8) * D_ + j0) = make_float2(y0, y1);
            } else {
                __nv_bfloat162 h0 = __floats2bfloat162_rn(x0, x1);
                __nv_bfloat162 l0 = __floats2bfloat162_rn(x0 - __low2float(h0),
                                                          x1 - __high2float(h0));
                __nv_bfloat162 h1 = __floats2bfloat162_rn(y0, y1);
                __nv_bfloat162 l1 = __floats2bfloat162_rn(y0 - __low2float(h1),
                                                          y1 - __high2float(h1));
                size_t w0 = (size_t)i0 * DW_ + (j0 >> 1);
                size_t w1 = (size_t)(i0 + 8) * DW_ + (j0 >> 1);
                Ch[w0] = *(uint32_t*)&h0;  Cl[w0] = *(uint32_t*)&l0;
                Ch[w1] = *(uint32_t*)&h1;  Cl[w1] = *(uint32_t*)&l1;
            }
        }
    }
}

// ============================================================================
// Out projection (NN, bf16x3) with summed A: C = (A1+A2) @ W + b.
// ============================================================================
__global__ __launch_bounds__(256) void sgemm_sum2_nn_bias(
    const float* __restrict__ A1, const float* __restrict__ A2,
    const float* __restrict__ W,  const float* __restrict__ bias,
    float* __restrict__ C)
{
    const int bm = blockIdx.y * 128;
    const int bn = blockIdx.x * 128;
    const int tid = threadIdx.x;
    const int lane = tid & 31, wid = tid >> 5;
    const int warp_m = wid & 1, warp_n = wid >> 1;
    const int g = lane >> 2, tg = lane & 3;

    extern __shared__ uint32_t smw[];
    uint32_t* Ah = smw;
    uint32_t* Al = smw + TILE_W;
    uint32_t* Bh = smw + 2 * TILE_W;
    uint32_t* Bl = smw + 3 * TILE_W;

    float acc[4][4][4];
#pragma unroll
    for (int a = 0; a < 4; a++)
#pragma unroll
        for (int b = 0; b < 4; b++)
#pragma unroll
            for (int c = 0; c < 4; c++) acc[a][b][c] = 0.f;

    for (int k0 = 0; k0 < D_; k0 += 64) {
        ldcv_tile_sum2(Ah, Al, A1 + k0, A2 + k0, bm, D_, tid);
        ldcv_tile_t<128>(Bh, Bl, W + (size_t)k0 * D_ + bn, D_, tid);
        __syncthreads();
        tc_nt_mainloop_bf16(Ah, Al, Bh, Bl, warp_m, warp_n, g, tg, acc);
        __syncthreads();
    }

#pragma unroll
    for (int mt = 0; mt < 4; mt++) {
        const int i0 = bm + warp_m * 64 + mt * 16 + g;
#pragma unroll
        for (int nt = 0; nt < 4; nt++) {
            const int j0 = bn + warp_n * 32 + nt * 8 + 2 * tg;
            float b0 = bias[j0], b1 = bias[j0 + 1];
            *(float2*)(C + (size_t)i0 * D_ + j0) =
                make_float2(acc[mt][nt][0] + b0, acc[mt][nt][1] + b1);
            *(float2*)(C + (size_t)(i0 + 8) * D_ + j0) =
                make_float2(acc[mt][nt][2] + b0, acc[mt][nt][3] + b1);
        }
    }
}

// ============================================================================
// Causal row softmax (R13 version: full-row stores incl. exact-zero tail).
// ============================================================================
__global__ void softmax_causal(float* __restrict__ attn)
{
    const int row = blockIdx.x;
    const int i   = row & (S_ - 1);
    float* p = attn + (size_t)row * S_;
    const int tid = threadIdx.x;

    float r[8];
    float mx = -1e30f;
#pragma unroll
    for (int l = 0; l < 8; l++) {
        int j = tid + (l << 8);
        r[l] = (j <= i) ? p[j] : -1e30f;
        mx = fmaxf(mx, r[l]);
    }
#pragma unroll
    for (int o = 16; o > 0; o >>= 1)
        mx = fmaxf(mx, __shfl_xor_sync(0xffffffffu, mx, o));
    __shared__ float smx[8];
    __shared__ float ssum[8];
    if ((tid & 31) == 0) smx[tid >> 5] = mx;
    __syncthreads();
#pragma unroll
    for (int w = 0; w < 8; w++) mx = fmaxf(mx, smx[w]);

    float sum = 0.f;
#pragma unroll
    for (int l = 0; l < 8; l++) {
        int j = tid + (l << 8);
        r[l] = (j <= i) ? __expf(r[l] - mx) : 0.f;
        sum += r[l];
    }
#pragma unroll
    for (int o = 16; o > 0; o >>= 1)
        sum += __shfl_xor_sync(0xffffffffu, sum, o);
    if ((tid & 31) == 0) ssum[tid >> 5] = sum;
    __syncthreads();
    float tot = 0.f;
#pragma unroll
    for (int w = 0; w < 8; w++) tot += ssum[w];
    const float inv = 1.f / tot;

#pragma unroll
    for (int l = 0; l < 8; l++) p[tid + (l << 8)] = r[l] * inv;
}

// ============================================================================
// AV GEMM (NN, bf16x3): causal, split-K x2, heavy tiles first (R13 version).
// ============================================================================
__global__ __launch_bounds__(256) void av_kernel(
    const float* __restrict__ attn, const float* __restrict__ Vp,
    float* __restrict__ O0, float* __restrict__ O1)
{
    const int bh = blockIdx.z;
    const int b = bh >> 3, h = bh & 7;
    const int bm = (15 - blockIdx.y) * 128;
    const int kend = bm + 128;
    const int half = kend >> 1;
    const int kbeg = blockIdx.x * half;
    const int kfin = kbeg + half;
    float* Ot = blockIdx.x ? O1 : O0;

    const float* Ar = attn + (size_t)bh * S_ * S_;
    const float* Vr = Vp + (size_t)b * S_ * D_ + h * DH_;
    const int tid = threadIdx.x;
    const int lane = tid & 31, wid = tid >> 5;
    const int warp_m = wid & 3, warp_n = wid >> 2;
    const int g = lane >> 2, tg = lane & 3;

    extern __shared__ uint32_t smw[];
    uint32_t* Ah = smw;
    uint32_t* Al = smw + TILE_W;
    uint32_t* Bh = smw + 2 * TILE_W;
    uint32_t* Bl = smw + 2 * TILE_W + TILE_W64;

    float acc[2][4][4];
#pragma unroll
    for (int a = 0; a < 2; a++)
#pragma unroll
        for (int c = 0; c < 4; c++)
#pragma unroll
            for (int d = 0; d < 4; d++) acc[a][c][d] = 0.f;

    for (int k0 = kbeg; k0 < kfin; k0 += 64) {
        ldcv_tile(Ah, Al, Ar + k0, bm, S_, tid);
        ldcv_tile_t<64>(Bh, Bl, Vr + (size_t)k0 * D_, D_, tid);
        __syncthreads();
        tc_nt_mainloop_bf16_av(Ah, Al, Bh, Bl, warp_m, warp_n, g, tg, acc);
        __syncthreads();
    }

    float* Ob = Ot + (size_t)b * S_ * D_ + h * DH_;
#pragma unroll
    for (int mt = 0; mt < 2; mt++) {
        const int i0 = bm + warp_m * 32 + mt * 16 + g;
#pragma unroll
        for (int nt = 0; nt < 4; nt++) {
            const int j0 = warp_n * 32 + nt * 8 + 2 * tg;
            *(float2*)(Ob + (size_t)i0 * D_ + j0) =
                make_float2(acc[mt][nt][0], acc[mt][nt][1]);
            *(float2*)(Ob + (size_t)(i0 + 8) * D_ + j0) =
                make_float2(acc[mt][nt][2], acc[mt][nt][3]);
        }
    }
}

// ============================================================================
// launch
// ============================================================================
extern "C" void kernel_launch(void* const* d_in, const int* in_sizes, int n_in,
                              void* d_out, int out_size)
{
    const float* v  = (const float*)d_in[0];
    const float* k  = (const float*)d_in[1];
    const float* q  = (const float*)d_in[2];
    // d_in[3] = mask (implemented analytically)
    const float* Wq = (const float*)d_in[4];
    const float* bq = (const float*)d_in[5];
    const float* Wk = (const float*)d_in[6];
    const float* bk = (const float*)d_in[7];
    const float* Wv = (const float*)d_in[8];
    const float* bv = (const float*)d_in[9];
    const float* Wo = (const float*)d_in[10];
    const float* bo = (const float*)d_in[11];
    const float* E  = (const float*)d_in[12];

    float* out  = (float*)d_out;                       // (B,S,D)
    float* attn = (float*)d_out + (size_t)B_*S_*D_;    // (B,H,S,S)

    uint32_t *Qh, *Ql, *Kh, *Kl;
    float *Vp, *Tmp, *Tmp2;
    __half* QE;
    cudaGetSymbolAddress((void**)&Qh,   g_Qh);
    cudaGetSymbolAddress((void**)&Ql,   g_Ql);
    cudaGetSymbolAddress((void**)&Kh,   g_Kh);
    cudaGetSymbolAddress((void**)&Kl,   g_Kl);
    cudaGetSymbolAddress((void**)&Vp,   g_Vp);
    cudaGetSymbolAddress((void**)&Tmp,  g_tmp);
    cudaGetSymbolAddress((void**)&Tmp2, g_tmp2);
    cudaGetSymbolAddress((void**)&QE,   g_QE);

    static int attr_done = 0;
    if (!attr_done) {
        cudaFuncSetAttribute(logits_kernel,      cudaFuncAttributeMaxDynamicSharedMemorySize, SMEM_TC);
        cudaFuncSetAttribute(proj_qkv,           cudaFuncAttributeMaxDynamicSharedMemorySize, SMEM_TC);
        cudaFuncSetAttribute(sgemm_sum2_nn_bias, cudaFuncAttributeMaxDynamicSharedMemorySize, SMEM_TC);
        cudaFuncSetAttribute(av_kernel,          cudaFuncAttributeMaxDynamicSharedMemorySize, SMEM_AV);
        attr_done = 1;
    }

    dim3 gProj(D_ / 128, (B_*S_) / 128, 3);  // (4, 32, 3)
    proj_qkv<<<gProj, 256, SMEM_TC>>>(q, k, v, Wq, bq, Wk, bk, Wv, bv,
                                      Qh, Ql, Kh, Kl, Vp);

    dim3 gQE(MM_ / 128, S_ / 128, BH_);      // triangular early-exit
    gemm_qe<<<gQE, 256, SMEM_QE>>>(Qh, E, QE);

    dim3 gLg(S_ / 128, S_ / 128, BH_);       // upper tiles early-exit
    logits_kernel<<<gLg, 256, SMEM_TC>>>(Qh, Ql, Kh, Kl, QE, attn);

    softmax_causal<<<BH_ * S_, 256>>>(attn);

    dim3 gAV(2, S_ / 128, BH_);              // split-K x2
    av_kernel<<<gAV, 256, SMEM_AV>>>(attn, Vp, Tmp, Tmp2);

    dim3 gOut(D_ / 128, (B_*S_) / 128);
    sgemm_sum2_nn_bias<<<gOut, 256, SMEM_TC>>>(Tmp, Tmp2, Wo, bo, out);
}

// round 16
// speedup vs baseline: 1.3334x; 1.1014x over previous
#include <cuda_runtime.h>
#include <cuda_bf16.h>
#include <cuda_fp16.h>
#include <cstdint>

#define B_  2
#define S_  2048
#define D_  512
#define H_  8
#define DH_ 64
#define MM_ 2048          // MAX_SEQ (== S here)
#define BH_ (B_*H_)
#define DW_ (D_/2)        // packed words per row
#define DHW_ (DH_/2)      // packed words per head

// ---------------- scratch (static __device__, no allocation) ----------------
__device__ uint32_t g_Qh[B_*S_*DW_];             // 4 MB  Q hi (bf16x2 packed)
__device__ uint32_t g_Ql[B_*S_*DW_];             // 4 MB  Q lo
__device__ uint32_t g_Kh[B_*S_*DW_];             // 4 MB  K hi
__device__ uint32_t g_Kl[B_*S_*DW_];             // 4 MB  K lo
__device__ float    g_Vp[B_*S_*D_];              // 8 MB  V (fp32)
__device__ float    g_tmp[B_*S_*D_];             // 8 MB  (AV partial, k-half 0)
__device__ float    g_tmp2[B_*S_*D_];            // 8 MB  (AV partial, k-half 1)
__device__ __half   g_QE[(size_t)BH_*S_*MM_];    // 128 MB (Q @ E^T, fp16)

// ---------------- bf16 mma helper ----------------
__device__ __forceinline__ void mma_bf16(float c[4],
    uint32_t a0, uint32_t a1, uint32_t a2, uint32_t a3,
    uint32_t b0, uint32_t b1)
{
    asm volatile(
        "mma.sync.aligned.m16n8k16.row.col.f32.bf16.bf16.f32 "
        "{%0,%1,%2,%3}, {%4,%5,%6,%7}, {%8,%9}, {%0,%1,%2,%3};"
        : "+f"(c[0]), "+f"(c[1]), "+f"(c[2]), "+f"(c[3])
        : "r"(a0), "r"(a1), "r"(a2), "r"(a3), "r"(b0), "r"(b1));
}

// smem word layout: tile[rows][PADW] of uint32, word = bf16x2(k even, k odd).
#define PADW 36
#define TILE_W (128 * PADW)
#define TILE_W64 (64 * PADW)
#define SMEM_TC (4 * TILE_W * 4)                  // 73728 B
#define SMEM_AV ((2 * TILE_W + 2 * TILE_W64) * 4) // 55296 B
#define SMEM_QE (2 * TILE_W * 4)                  // 36864 B

// packed-word tile load: gmem uint32 [128 x 32 words] -> smem, NO conversion
__device__ __forceinline__ void ld_tile_pk(
    uint32_t* __restrict__ dst, const uint32_t* __restrict__ src,
    int row0, int ldw, int tid)
{
#pragma unroll
    for (int l = 0; l < 4; l++) {
        int vv = tid + l * 256;
        int row = vv >> 3, c = (vv & 7) * 4;
        uint4 a = *(const uint4*)(src + (size_t)(row0 + row) * ldw + c);
        *(uint4*)&dst[row * PADW + c] = a;
    }
}

// gmem fp32 [128 x 64] k-contiguous tile -> smem bf16 hi/lo packed (AV path)
__device__ __forceinline__ void ldcv_tile(
    uint32_t* __restrict__ hi, uint32_t* __restrict__ lo,
    const float* __restrict__ src, int row0, int ld, int tid)
{
#pragma unroll
    for (int l = 0; l < 8; l++) {
        int vv = tid + l * 256;
        int row = vv >> 4, c4 = (vv & 15) * 4;
        float4 a = *(const float4*)(src + (size_t)(row0 + row) * ld + c4);
        __nv_bfloat162 h0 = __floats2bfloat162_rn(a.x, a.y);   // .x = low = k even
        __nv_bfloat162 h1 = __floats2bfloat162_rn(a.z, a.w);
        float lx = a.x - __low2float(h0),  ly = a.y - __high2float(h0);
        float lz = a.z - __low2float(h1),  lw = a.w - __high2float(h1);
        __nv_bfloat162 l0 = __floats2bfloat162_rn(lx, ly);
        __nv_bfloat162 l1 = __floats2bfloat162_rn(lz, lw);
        int kw = row * PADW + (c4 >> 1);
        hi[kw]     = *(uint32_t*)&h0;  hi[kw + 1] = *(uint32_t*)&h1;
        lo[kw]     = *(uint32_t*)&l0;  lo[kw + 1] = *(uint32_t*)&l1;
    }
}

// hi-only variant (QE E-side: E input is fp32)
__device__ __forceinline__ void ldcv_tile_hi(
    uint32_t* __restrict__ hi,
    const float* __restrict__ src, int row0, int ld, int tid)
{
#pragma unroll
    for (int l = 0; l < 8; l++) {
        int vv = tid + l * 256;
        int row = vv >> 4, c4 = (vv & 15) * 4;
        float4 a = *(const float4*)(src + (size_t)(row0 + row) * ld + c4);
        __nv_bfloat162 h0 = __floats2bfloat162_rn(a.x, a.y);
        __nv_bfloat162 h1 = __floats2bfloat162_rn(a.z, a.w);
        int kw = row * PADW + (c4 >> 1);
        hi[kw]     = *(uint32_t*)&h0;  hi[kw + 1] = *(uint32_t*)&h1;
    }
}

// A = A1 + A2 (out-projection)
__device__ __forceinline__ void ldcv_tile_sum2(
    uint32_t* __restrict__ hi, uint32_t* __restrict__ lo,
    const float* __restrict__ s1, const float* __restrict__ s2,
    int row0, int ld, int tid)
{
#pragma unroll
    for (int l = 0; l < 8; l++) {
        int vv = tid + l * 256;
        int row = vv >> 4, c4 = (vv & 15) * 4;
        size_t off = (size_t)(row0 + row) * ld + c4;
        float4 a = *(const float4*)(s1 + off);
        float4 b = *(const float4*)(s2 + off);
        a.x += b.x; a.y += b.y; a.z += b.z; a.w += b.w;
        __nv_bfloat162 h0 = __floats2bfloat162_rn(a.x, a.y);
        __nv_bfloat162 h1 = __floats2bfloat162_rn(a.z, a.w);
        float lx = a.x - __low2float(h0),  ly = a.y - __high2float(h0);
        float lz = a.z - __low2float(h1),  lw = a.w - __high2float(h1);
        __nv_bfloat162 l0 = __floats2bfloat162_rn(lx, ly);
        __nv_bfloat162 l1 = __floats2bfloat162_rn(lz, lw);
        int kw = row * PADW + (c4 >> 1);
        hi[kw]     = *(uint32_t*)&h0;  hi[kw + 1] = *(uint32_t*)&h1;
        lo[kw]     = *(uint32_t*)&l0;  lo[kw + 1] = *(uint32_t*)&l1;
    }
}

// transpose-load: gmem fp32 chunk [64 k][N n] (k-major) -> Bs[n][kpair] hi/lo.
template<int N>
__device__ __forceinline__ void ldcv_tile_t(
    uint32_t* __restrict__ hi, uint32_t* __restrict__ lo,
    const float* __restrict__ src, int ld, int tid)
{
#pragma unroll
    for (int l = 0; l < (32 * (N / 4)) / 256; l++) {
        int idx = tid + l * 256;
        int nq = idx >> 5;
        int kp = idx & 31;
        int n = nq * 4;
        float4 r0 = *(const float4*)(src + (size_t)(kp * 2)     * ld + n);
        float4 r1 = *(const float4*)(src + (size_t)(kp * 2 + 1) * ld + n);
        float a0[4] = {r0.x, r0.y, r0.z, r0.w};
        float a1[4] = {r1.x, r1.y, r1.z, r1.w};
#pragma unroll
        for (int i = 0; i < 4; i++) {
            __nv_bfloat162 h = __floats2bfloat162_rn(a0[i], a1[i]);
            float lx = a0[i] - __low2float(h);
            float ly = a1[i] - __high2float(h);
            __nv_bfloat162 l2 = __floats2bfloat162_rn(lx, ly);
            hi[(n + i) * PADW + kp] = *(uint32_t*)&h;
            lo[(n + i) * PADW + kp] = *(uint32_t*)&l2;
        }
    }
}

// ============================================================================
// bf16x3 mainloop (3-pass)
// ============================================================================
__device__ __forceinline__ void tc_nt_mainloop_bf16(
    const uint32_t* __restrict__ Ah, const uint32_t* __restrict__ Al,
    const uint32_t* __restrict__ Bh, const uint32_t* __restrict__ Bl,
    int warp_m, int warp_n, int g, int tg, float acc[4][4][4])
{
#pragma unroll
    for (int ks = 0; ks < 4; ks++) {
        const int base = ks * 8;
        uint32_t bh0[4], bh1[4], bl0[4], bl1[4];
#pragma unroll
        for (int nt = 0; nt < 4; nt++) {
            const int n0 = (warp_n * 32 + nt * 8 + g) * PADW + base + tg;
            bh0[nt] = Bh[n0]; bh1[nt] = Bh[n0 + 4];
            bl0[nt] = Bl[n0]; bl1[nt] = Bl[n0 + 4];
        }
#pragma unroll
        for (int mt = 0; mt < 4; mt++) {
            const int r0 = (warp_m * 64 + mt * 16 + g) * PADW + base + tg;
            const int r1 = r0 + 8 * PADW;
            uint32_t ah0 = Ah[r0], ah1 = Ah[r1], ah2 = Ah[r0 + 4], ah3 = Ah[r1 + 4];
            uint32_t al0 = Al[r0], al1 = Al[r1], al2 = Al[r0 + 4], al3 = Al[r1 + 4];
#pragma unroll
            for (int nt = 0; nt < 4; nt++) {
                mma_bf16(acc[mt][nt], ah0, ah1, ah2, ah3, bh0[nt], bh1[nt]);
                mma_bf16(acc[mt][nt], ah0, ah1, ah2, ah3, bl0[nt], bl1[nt]);
                mma_bf16(acc[mt][nt], al0, al1, al2, al3, bh0[nt], bh1[nt]);
            }
        }
    }
}

// single-pass (hi only)
__device__ __forceinline__ void tc_nt_mainloop_bf16_hi(
    const uint32_t* __restrict__ Ah, const uint32_t* __restrict__ Bh,
    int warp_m, int warp_n, int g, int tg, float acc[4][4][4])
{
#pragma unroll
    for (int ks = 0; ks < 4; ks++) {
        const int base = ks * 8;
        uint32_t bh0[4], bh1[4];
#pragma unroll
        for (int nt = 0; nt < 4; nt++) {
            const int n0 = (warp_n * 32 + nt * 8 + g) * PADW + base + tg;
            bh0[nt] = Bh[n0]; bh1[nt] = Bh[n0 + 4];
        }
#pragma unroll
        for (int mt = 0; mt < 4; mt++) {
            const int r0 = (warp_m * 64 + mt * 16 + g) * PADW + base + tg;
            const int r1 = r0 + 8 * PADW;
            uint32_t ah0 = Ah[r0], ah1 = Ah[r1], ah2 = Ah[r0 + 4], ah3 = Ah[r1 + 4];
#pragma unroll
            for (int nt = 0; nt < 4; nt++)
                mma_bf16(acc[mt][nt], ah0, ah1, ah2, ah3, bh0[nt], bh1[nt]);
        }
    }
}

// AV variant: BM=128 x BN=64.
__device__ __forceinline__ void tc_nt_mainloop_bf16_av(
    const uint32_t* __restrict__ Ah, const uint32_t* __restrict__ Al,
    const uint32_t* __restrict__ Bh, const uint32_t* __restrict__ Bl,
    int warp_m, int warp_n, int g, int tg, float acc[2][4][4])
{
#pragma unroll
    for (int ks = 0; ks < 4; ks++) {
        const int base = ks * 8;
        uint32_t bh0[4], bh1[4], bl0[4], bl1[4];
#pragma unroll
        for (int nt = 0; nt < 4; nt++) {
            const int n0 = (warp_n * 32 + nt * 8 + g) * PADW + base + tg;
            bh0[nt] = Bh[n0]; bh1[nt] = Bh[n0 + 4];
            bl0[nt] = Bl[n0]; bl1[nt] = Bl[n0 + 4];
        }
#pragma unroll
        for (int mt = 0; mt < 2; mt++) {
            const int r0 = (warp_m * 32 + mt * 16 + g) * PADW + base + tg;
            const int r1 = r0 + 8 * PADW;
            uint32_t ah0 = Ah[r0], ah1 = Ah[r1], ah2 = Ah[r0 + 4], ah3 = Ah[r1 + 4];
            uint32_t al0 = Al[r0], al1 = Al[r1], al2 = Al[r0 + 4], al3 = Al[r1 + 4];
#pragma unroll
            for (int nt = 0; nt < 4; nt++) {
                mma_bf16(acc[mt][nt], ah0, ah1, ah2, ah3, bh0[nt], bh1[nt]);
                mma_bf16(acc[mt][nt], ah0, ah1, ah2, ah3, bl0[nt], bl1[nt]);
                mma_bf16(acc[mt][nt], al0, al1, al2, al3, bh0[nt], bh1[nt]);
            }
        }
    }
}

// ============================================================================
// QE GEMM (NT, single-pass bf16), per-tile grid, Q from packed hi plane.
// ============================================================================
__global__ __launch_bounds__(256) void gemm_qe(
    const uint32_t* __restrict__ Qh, const float* __restrict__ E,
    __half* __restrict__ QE)
{
    if (blockIdx.x + blockIdx.y < 15) return;   // never-read tiles
    const int bh = blockIdx.z;
    const uint32_t* A = Qh + (size_t)(bh >> 3) * S_ * DW_ + (bh & 7) * DHW_;
    const int bm = blockIdx.y * 128;
    const int bn = blockIdx.x * 128;
    const int tid = threadIdx.x;
    const int lane = tid & 31, wid = tid >> 5;
    const int warp_m = wid & 1, warp_n = wid >> 1;
    const int g = lane >> 2, tg = lane & 3;

    extern __shared__ uint32_t smw[];
    uint32_t* Ah = smw;
    uint32_t* Bh = smw + TILE_W;

    ld_tile_pk(Ah, A, bm, DW_, tid);            // direct copy, no cvt
    ldcv_tile_hi(Bh, E, bn, DH_, tid);
    __syncthreads();

    float acc[4][4][4];
#pragma unroll
    for (int a = 0; a < 4; a++)
#pragma unroll
        for (int b = 0; b < 4; b++)
#pragma unroll
            for (int c = 0; c < 4; c++) acc[a][b][c] = 0.f;

    tc_nt_mainloop_bf16_hi(Ah, Bh, warp_m, warp_n, g, tg, acc);

    __half* Cb = QE + (size_t)bh * S_ * MM_;
#pragma unroll
    for (int mt = 0; mt < 4; mt++) {
        const int i0 = bm + warp_m * 64 + mt * 16 + g;
#pragma unroll
        for (int nt = 0; nt < 4; nt++) {
            const int j0 = bn + warp_n * 32 + nt * 8 + 2 * tg;
            *(__half2*)(Cb + (size_t)i0 * MM_ + j0) =
                __floats2half2_rn(acc[mt][nt][0], acc[mt][nt][1]);
            *(__half2*)(Cb + (size_t)(i0 + 8) * MM_ + j0) =
                __floats2half2_rn(acc[mt][nt][2], acc[mt][nt][3]);
        }
    }
}

// ============================================================================
// Logits (NT, causal, bf16x3), per-tile grid, Q/K from packed planes.
// Epilogue split: full (bn<bm) tiles take unguarded float2-store path;
// diagonal tiles keep the guarded scalar path.  Arithmetic identical.
// ============================================================================
__global__ __launch_bounds__(256) void logits_kernel(
    const uint32_t* __restrict__ Qh, const uint32_t* __restrict__ Ql,
    const uint32_t* __restrict__ Kh, const uint32_t* __restrict__ Kl,
    const __half* __restrict__ QE, float* __restrict__ attn)
{
    const int bm = blockIdx.y * 128;
    const int bn = blockIdx.x * 128;
    if (bn > bm + 127) return;
    const int bh = blockIdx.z;
    const size_t hoff = (size_t)(bh >> 3) * S_ * DW_ + (bh & 7) * DHW_;
    const int tid = threadIdx.x;
    const int lane = tid & 31, wid = tid >> 5;
    const int warp_m = wid & 1, warp_n = wid >> 1;
    const int g = lane >> 2, tg = lane & 3;

    extern __shared__ uint32_t smw[];
    uint32_t* Ah = smw;
    uint32_t* Al = smw + TILE_W;
    uint32_t* Bh = smw + 2 * TILE_W;
    uint32_t* Bl = smw + 3 * TILE_W;

    ld_tile_pk(Ah, Qh + hoff, bm, DW_, tid);
    ld_tile_pk(Al, Ql + hoff, bm, DW_, tid);
    ld_tile_pk(Bh, Kh + hoff, bn, DW_, tid);
    ld_tile_pk(Bl, Kl + hoff, bn, DW_, tid);
    __syncthreads();

    float acc[4][4][4];
#pragma unroll
    for (int a = 0; a < 4; a++)
#pragma unroll
        for (int b = 0; b < 4; b++)
#pragma unroll
            for (int c = 0; c < 4; c++) acc[a][b][c] = 0.f;

    tc_nt_mainloop_bf16(Ah, Al, Bh, Bl, warp_m, warp_n, g, tg, acc);

    const __half* QEr = QE + (size_t)bh * S_ * MM_;
    float* Cb = attn + (size_t)bh * S_ * S_;

    if (bn < bm) {
        // fully unmasked tile: no predicates, float2 stores
#pragma unroll
        for (int mt = 0; mt < 4; mt++) {
            const int ia = bm + warp_m * 64 + mt * 16 + g;
            const int ib = ia + 8;
            const __half* qa = QEr + (size_t)ia * MM_ + (MM_ - 1 - ia);
            const __half* qb = QEr + (size_t)ib * MM_ + (MM_ - 1 - ib);
            float* ca = Cb + (size_t)ia * S_;
            float* cbp = Cb + (size_t)ib * S_;
#pragma unroll
            for (int nt = 0; nt < 4; nt++) {
                const int j0 = bn + warp_n * 32 + nt * 8 + 2 * tg;
                float2 oa, ob;
                oa.x = (acc[mt][nt][0] + __half2float(qa[j0]))     * 0.125f;
                oa.y = (acc[mt][nt][1] + __half2float(qa[j0 + 1])) * 0.125f;
                ob.x = (acc[mt][nt][2] + __half2float(qb[j0]))     * 0.125f;
                ob.y = (acc[mt][nt][3] + __half2float(qb[j0 + 1])) * 0.125f;
                *(float2*)(ca + j0)  = oa;
                *(float2*)(cbp + j0) = ob;
            }
        }
    } else {
        // diagonal tile: guarded scalar path
#pragma unroll
        for (int mt = 0; mt < 4; mt++) {
            const int ia = bm + warp_m * 64 + mt * 16 + g;
            const int ib = ia + 8;
#pragma unroll
            for (int nt = 0; nt < 4; nt++) {
                const int j0 = bn + warp_n * 32 + nt * 8 + 2 * tg;
                const int j1 = j0 + 1;
                if (j0 <= ia)
                    Cb[(size_t)ia * S_ + j0] =
                        (acc[mt][nt][0] + __half2float(QEr[(size_t)ia * MM_ + (j0 - ia + MM_ - 1)])) * 0.125f;
                if (j1 <= ia)
                    Cb[(size_t)ia * S_ + j1] =
                        (acc[mt][nt][1] + __half2float(QEr[(size_t)ia * MM_ + (j1 - ia + MM_ - 1)])) * 0.125f;
                if (j0 <= ib)
                    Cb[(size_t)ib * S_ + j0] =
                        (acc[mt][nt][2] + __half2float(QEr[(size_t)ib * MM_ + (j0 - ib + MM_ - 1)])) * 0.125f;
                if (j1 <= ib)
                    Cb[(size_t)ib * S_ + j1] =
                        (acc[mt][nt][3] + __half2float(QEr[(size_t)ib * MM_ + (j1 - ib + MM_ - 1)])) * 0.125f;
            }
        }
    }
}

// ============================================================================
// Fused QKV projection (NN, bf16x3): Q,K written as packed bf16 hi/lo planes;
// V written fp32.
// ============================================================================
__global__ __launch_bounds__(256) void proj_qkv(
    const float* __restrict__ q,  const float* __restrict__ k,
    const float* __restrict__ v,
    const float* __restrict__ Wq, const float* __restrict__ bq,
    const float* __restrict__ Wk, const float* __restrict__ bk,
    const float* __restrict__ Wv, const float* __restrict__ bv,
    uint32_t* __restrict__ Qh, uint32_t* __restrict__ Ql,
    uint32_t* __restrict__ Kh, uint32_t* __restrict__ Kl,
    float* __restrict__ Vp)
{
    const float *A, *W, *bias;
    uint32_t *Ch = nullptr, *Cl = nullptr;
    if (blockIdx.z == 0)      { A = q; W = Wq; bias = bq; Ch = Qh; Cl = Ql; }
    else if (blockIdx.z == 1) { A = k; W = Wk; bias = bk; Ch = Kh; Cl = Kl; }
    else                      { A = v; W = Wv; bias = bv; }

    const int bm = blockIdx.y * 128;
    const int bn = blockIdx.x * 128;
    const int tid = threadIdx.x;
    const int lane = tid & 31, wid = tid >> 5;
    const int warp_m = wid & 1, warp_n = wid >> 1;
    const int g = lane >> 2, tg = lane & 3;

    extern __shared__ uint32_t smw[];
    uint32_t* Ah = smw;
    uint32_t* Al = smw + TILE_W;
    uint32_t* Bh = smw + 2 * TILE_W;
    uint32_t* Bl = smw + 3 * TILE_W;

    float acc[4][4][4];
#pragma unroll
    for (int a = 0; a < 4; a++)
#pragma unroll
        for (int b = 0; b < 4; b++)
#pragma unroll
            for (int c = 0; c < 4; c++) acc[a][b][c] = 0.f;

    for (int k0 = 0; k0 < D_; k0 += 64) {
        ldcv_tile(Ah, Al, A + k0, bm, D_, tid);
        ldcv_tile_t<128>(Bh, Bl, W + (size_t)k0 * D_ + bn, D_, tid);
        __syncthreads();
        tc_nt_mainloop_bf16(Ah, Al, Bh, Bl, warp_m, warp_n, g, tg, acc);
        __syncthreads();
    }

#pragma unroll
    for (int mt = 0; mt < 4; mt++) {
        const int i0 = bm + warp_m * 64 + mt * 16 + g;
#pragma unroll
        for (int nt = 0; nt < 4; nt++) {
            const int j0 = bn + warp_n * 32 + nt * 8 + 2 * tg;
            float b0 = bias[j0], b1 = bias[j0 + 1];
            float x0 = acc[mt][nt][0] + b0, x1 = acc[mt][nt][1] + b1;
            float y0 = acc[mt][nt][2] + b0, y1 = acc[mt][nt][3] + b1;
            if (blockIdx.z == 2) {
                *(float2*)(Vp + (size_t)i0 * D_ + j0)       = make_float2(x0, x1);
                *(float2*)(Vp + (size_t)(i0 + 8) * D_ + j0) = make_float2(y0, y1);
            } else {
                __nv_bfloat162 h0 = __floats2bfloat162_rn(x0, x1);
                __nv_bfloat162 l0 = __floats2bfloat162_rn(x0 - __low2float(h0),
                                                          x1 - __high2float(h0));
                __nv_bfloat162 h1 = __floats2bfloat162_rn(y0, y1);
                __nv_bfloat162 l1 = __floats2bfloat162_rn(y0 - __low2float(h1),
                                                          y1 - __high2float(h1));
                size_t w0 = (size_t)i0 * DW_ + (j0 >> 1);
                size_t w1 = (size_t)(i0 + 8) * DW_ + (j0 >> 1);
                Ch[w0] = *(uint32_t*)&h0;  Cl[w0] = *(uint32_t*)&l0;
                Ch[w1] = *(uint32_t*)&h1;  Cl[w1] = *(uint32_t*)&l1;
            }
        }
    }
}

// ============================================================================
// Out projection (NN, bf16x3) with summed A: C = (A1+A2) @ W + b.
// ============================================================================
__global__ __launch_bounds__(256) void sgemm_sum2_nn_bias(
    const float* __restrict__ A1, const float* __restrict__ A2,
    const float* __restrict__ W,  const float* __restrict__ bias,
    float* __restrict__ C)
{
    const int bm = blockIdx.y * 128;
    const int bn = blockIdx.x * 128;
    const int tid = threadIdx.x;
    const int lane = tid & 31, wid = tid >> 5;
    const int warp_m = wid & 1, warp_n = wid >> 1;
    const int g = lane >> 2, tg = lane & 3;

    extern __shared__ uint32_t smw[];
    uint32_t* Ah = smw;
    uint32_t* Al = smw + TILE_W;
    uint32_t* Bh = smw + 2 * TILE_W;
    uint32_t* Bl = smw + 3 * TILE_W;

    float acc[4][4][4];
#pragma unroll
    for (int a = 0; a < 4; a++)
#pragma unroll
        for (int b = 0; b < 4; b++)
#pragma unroll
            for (int c = 0; c < 4; c++) acc[a][b][c] = 0.f;

    for (int k0 = 0; k0 < D_; k0 += 64) {
        ldcv_tile_sum2(Ah, Al, A1 + k0, A2 + k0, bm, D_, tid);
        ldcv_tile_t<128>(Bh, Bl, W + (size_t)k0 * D_ + bn, D_, tid);
        __syncthreads();
        tc_nt_mainloop_bf16(Ah, Al, Bh, Bl, warp_m, warp_n, g, tg, acc);
        __syncthreads();
    }

#pragma unroll
    for (int mt = 0; mt < 4; mt++) {
        const int i0 = bm + warp_m * 64 + mt * 16 + g;
#pragma unroll
        for (int nt = 0; nt < 4; nt++) {
            const int j0 = bn + warp_n * 32 + nt * 8 + 2 * tg;
            float b0 = bias[j0], b1 = bias[j0 + 1];
            *(float2*)(C + (size_t)i0 * D_ + j0) =
                make_float2(acc[mt][nt][0] + b0, acc[mt][nt][1] + b1);
            *(float2*)(C + (size_t)(i0 + 8) * D_ + j0) =
                make_float2(acc[mt][nt][2] + b0, acc[mt][nt][3] + b1);
        }
    }
}

// ============================================================================
// Causal row softmax (full-row stores incl. exact-zero tail).
// ============================================================================
__global__ void softmax_causal(float* __restrict__ attn)
{
    const int row = blockIdx.x;
    const int i   = row & (S_ - 1);
    float* p = attn + (size_t)row * S_;
    const int tid = threadIdx.x;

    float r[8];
    float mx = -1e30f;
#pragma unroll
    for (int l = 0; l < 8; l++) {
        int j = tid + (l << 8);
        r[l] = (j <= i) ? p[j] : -1e30f;
        mx = fmaxf(mx, r[l]);
    }
#pragma unroll
    for (int o = 16; o > 0; o >>= 1)
        mx = fmaxf(mx, __shfl_xor_sync(0xffffffffu, mx, o));
    __shared__ float smx[8];
    __shared__ float ssum[8];
    if ((tid & 31) == 0) smx[tid >> 5] = mx;
    __syncthreads();
#pragma unroll
    for (int w = 0; w < 8; w++) mx = fmaxf(mx, smx[w]);

    float sum = 0.f;
#pragma unroll
    for (int l = 0; l < 8; l++) {
        int j = tid + (l << 8);
        r[l] = (j <= i) ? __expf(r[l] - mx) : 0.f;
        sum += r[l];
    }
#pragma unroll
    for (int o = 16; o > 0; o >>= 1)
        sum += __shfl_xor_sync(0xffffffffu, sum, o);
    if ((tid & 31) == 0) ssum[tid >> 5] = sum;
    __syncthreads();
    float tot = 0.f;
#pragma unroll
    for (int w = 0; w < 8; w++) tot += ssum[w];
    const float inv = 1.f / tot;

#pragma unroll
    for (int l = 0; l < 8; l++) p[tid + (l << 8)] = r[l] * inv;
}

// ============================================================================
// AV GEMM (NN, bf16x3): causal, split-K x2, heavy tiles first.
// ============================================================================
__global__ __launch_bounds__(256) void av_kernel(
    const float* __restrict__ attn, const float* __restrict__ Vp,
    float* __restrict__ O0, float* __restrict__ O1)
{
    const int bh = blockIdx.z;
    const int b = bh >> 3, h = bh & 7;
    const int bm = (15 - blockIdx.y) * 128;
    const int kend = bm + 128;
    const int half = kend >> 1;
    const int kbeg = blockIdx.x * half;
    const int kfin = kbeg + half;
    float* Ot = blockIdx.x ? O1 : O0;

    const float* Ar = attn + (size_t)bh * S_ * S_;
    const float* Vr = Vp + (size_t)b * S_ * D_ + h * DH_;
    const int tid = threadIdx.x;
    const int lane = tid & 31, wid = tid >> 5;
    const int warp_m = wid & 3, warp_n = wid >> 2;
    const int g = lane >> 2, tg = lane & 3;

    extern __shared__ uint32_t smw[];
    uint32_t* Ah = smw;
    uint32_t* Al = smw + TILE_W;
    uint32_t* Bh = smw + 2 * TILE_W;
    uint32_t* Bl = smw + 2 * TILE_W + TILE_W64;

    float acc[2][4][4];
#pragma unroll
    for (int a = 0; a < 2; a++)
#pragma unroll
        for (int c = 0; c < 4; c++)
#pragma unroll
            for (int d = 0; d < 4; d++) acc[a][c][d] = 0.f;

    for (int k0 = kbeg; k0 < kfin; k0 += 64) {
        ldcv_tile(Ah, Al, Ar + k0, bm, S_, tid);
        ldcv_tile_t<64>(Bh, Bl, Vr + (size_t)k0 * D_, D_, tid);
        __syncthreads();
        tc_nt_mainloop_bf16_av(Ah, Al, Bh, Bl, warp_m, warp_n, g, tg, acc);
        __syncthreads();
    }

    float* Ob = Ot + (size_t)b * S_ * D_ + h * DH_;
#pragma unroll
    for (int mt = 0; mt < 2; mt++) {
        const int i0 = bm + warp_m * 32 + mt * 16 + g;
#pragma unroll
        for (int nt = 0; nt < 4; nt++) {
            const int j0 = warp_n * 32 + nt * 8 + 2 * tg;
            *(float2*)(Ob + (size_t)i0 * D_ + j0) =
                make_float2(acc[mt][nt][0], acc[mt][nt][1]);
            *(float2*)(Ob + (size_t)(i0 + 8) * D_ + j0) =
                make_float2(acc[mt][nt][2], acc[mt][nt][3]);
        }
    }
}

// ============================================================================
// launch
// ============================================================================
extern "C" void kernel_launch(void* const* d_in, const int* in_sizes, int n_in,
                              void* d_out, int out_size)
{
    const float* v  = (const float*)d_in[0];
    const float* k  = (const float*)d_in[1];
    const float* q  = (const float*)d_in[2];
    // d_in[3] = mask (implemented analytically)
    const float* Wq = (const float*)d_in[4];
    const float* bq = (const float*)d_in[5];
    const float* Wk = (const float*)d_in[6];
    const float* bk = (const float*)d_in[7];
    const float* Wv = (const float*)d_in[8];
    const float* bv = (const float*)d_in[9];
    const float* Wo = (const float*)d_in[10];
    const float* bo = (const float*)d_in[11];
    const float* E  = (const float*)d_in[12];

    float* out  = (float*)d_out;                       // (B,S,D)
    float* attn = (float*)d_out + (size_t)B_*S_*D_;    // (B,H,S,S)

    uint32_t *Qh, *Ql, *Kh, *Kl;
    float *Vp, *Tmp, *Tmp2;
    __half* QE;
    cudaGetSymbolAddress((void**)&Qh,   g_Qh);
    cudaGetSymbolAddress((void**)&Ql,   g_Ql);
    cudaGetSymbolAddress((void**)&Kh,   g_Kh);
    cudaGetSymbolAddress((void**)&Kl,   g_Kl);
    cudaGetSymbolAddress((void**)&Vp,   g_Vp);
    cudaGetSymbolAddress((void**)&Tmp,  g_tmp);
    cudaGetSymbolAddress((void**)&Tmp2, g_tmp2);
    cudaGetSymbolAddress((void**)&QE,   g_QE);

    static int attr_done = 0;
    if (!attr_done) {
        cudaFuncSetAttribute(logits_kernel,      cudaFuncAttributeMaxDynamicSharedMemorySize, SMEM_TC);
        cudaFuncSetAttribute(proj_qkv,           cudaFuncAttributeMaxDynamicSharedMemorySize, SMEM_TC);
        cudaFuncSetAttribute(sgemm_sum2_nn_bias, cudaFuncAttributeMaxDynamicSharedMemorySize, SMEM_TC);
        cudaFuncSetAttribute(av_kernel,          cudaFuncAttributeMaxDynamicSharedMemorySize, SMEM_AV);
        attr_done = 1;
    }

    dim3 gProj(D_ / 128, (B_*S_) / 128, 3);  // (4, 32, 3)
    proj_qkv<<<gProj, 256, SMEM_TC>>>(q, k, v, Wq, bq, Wk, bk, Wv, bv,
                                      Qh, Ql, Kh, Kl, Vp);

    dim3 gQE(MM_ / 128, S_ / 128, BH_);      // triangular early-exit
    gemm_qe<<<gQE, 256, SMEM_QE>>>(Qh, E, QE);

    dim3 gLg(S_ / 128, S_ / 128, BH_);       // upper tiles early-exit
    logits_kernel<<<gLg, 256, SMEM_TC>>>(Qh, Ql, Kh, Kl, QE, attn);

    softmax_causal<<<BH_ * S_, 256>>>(attn);

    dim3 gAV(2, S_ / 128, BH_);              // split-K x2
    av_kernel<<<gAV, 256, SMEM_AV>>>(attn, Vp, Tmp, Tmp2);

    dim3 gOut(D_ / 128, (B_*S_) / 128);
    sgemm_sum2_nn_bias<<<gOut, 256, SMEM_TC>>>(Tmp, Tmp2, Wo, bo, out);
}

// round 17
// speedup vs baseline: 1.4150x; 1.0612x over previous
#include <cuda_runtime.h>
#include <cuda_bf16.h>
#include <cuda_fp16.h>
#include <cstdint>

#define B_  2
#define S_  2048
#define D_  512
#define H_  8
#define DH_ 64
#define MM_ 2048          // MAX_SEQ (== S here)
#define BH_ (B_*H_)
#define DW_ (D_/2)        // packed words per row (256)
#define DHW_ (DH_/2)      // packed words per head (32)

// ---------------- scratch (static __device__, no allocation) ----------------
__device__ uint32_t g_Qh[B_*S_*DW_];             // 4 MB  Q hi (bf16x2 packed)
__device__ uint32_t g_Ql[B_*S_*DW_];             // 4 MB  Q lo
__device__ uint32_t g_Kh[B_*S_*DW_];             // 4 MB  K hi
__device__ uint32_t g_Kl[B_*S_*DW_];             // 4 MB  K lo
__device__ float    g_Vp[B_*S_*D_];              // 8 MB  V (fp32)
__device__ float    g_tmp[B_*S_*D_];             // 8 MB  (AV partial, k-half 0)
__device__ float    g_tmp2[B_*S_*D_];            // 8 MB  (AV partial, k-half 1)
__device__ __half   g_QE[(size_t)BH_*S_*MM_];    // 128 MB (Q @ E^T, fp16)
// pre-converted operands
__device__ uint32_t g_Wh[4*512*256];             // 2 MB  W hi planes [mat][n][kp]
__device__ uint32_t g_Wl[4*512*256];             // 2 MB  W lo planes
__device__ uint32_t g_Eh[MM_*DHW_];              // 256KB E hi plane [r][kp]
__device__ uint32_t g_Vth[BH_*DH_*(S_/2)];       // 4 MB  V^T hi [bh][d][jp]
__device__ uint32_t g_Vtl[BH_*DH_*(S_/2)];       // 4 MB  V^T lo

// ---------------- bf16 mma helper ----------------
__device__ __forceinline__ void mma_bf16(float c[4],
    uint32_t a0, uint32_t a1, uint32_t a2, uint32_t a3,
    uint32_t b0, uint32_t b1)
{
    asm volatile(
        "mma.sync.aligned.m16n8k16.row.col.f32.bf16.bf16.f32 "
        "{%0,%1,%2,%3}, {%4,%5,%6,%7}, {%8,%9}, {%0,%1,%2,%3};"
        : "+f"(c[0]), "+f"(c[1]), "+f"(c[2]), "+f"(c[3])
        : "r"(a0), "r"(a1), "r"(a2), "r"(a3), "r"(b0), "r"(b1));
}

__device__ __forceinline__ uint32_t pack_hi(float a, float b) {
    __nv_bfloat162 h = __floats2bfloat162_rn(a, b);
    return *(uint32_t*)&h;
}
__device__ __forceinline__ uint32_t pack_lo(float a, float b, uint32_t hw) {
    __nv_bfloat162 h = *(__nv_bfloat162*)&hw;
    __nv_bfloat162 l = __floats2bfloat162_rn(a - __low2float(h), b - __high2float(h));
    return *(uint32_t*)&l;
}

// smem word layout: tile[rows][PADW] of uint32, word = bf16x2(k even, k odd).
#define PADW 36
#define TILE_W (128 * PADW)
#define TILE_W64 (64 * PADW)
#define SMEM_TC (4 * TILE_W * 4)                  // 73728 B
#define SMEM_AV ((2 * TILE_W + 2 * TILE_W64) * 4) // 55296 B
#define SMEM_QE (2 * TILE_W * 4)                  // 36864 B

// packed-word tile load: gmem uint32 [128 x 32 words] -> smem, NO conversion
__device__ __forceinline__ void ld_tile_pk(
    uint32_t* __restrict__ dst, const uint32_t* __restrict__ src,
    int row0, int ldw, int tid)
{
#pragma unroll
    for (int l = 0; l < 4; l++) {
        int vv = tid + l * 256;
        int row = vv >> 3, c = (vv & 7) * 4;
        uint4 a = *(const uint4*)(src + (size_t)(row0 + row) * ldw + c);
        *(uint4*)&dst[row * PADW + c] = a;
    }
}

// 64-row variant (AV V tiles)
__device__ __forceinline__ void ld_tile_pk64(
    uint32_t* __restrict__ dst, const uint32_t* __restrict__ src,
    int ldw, int tid)
{
#pragma unroll
    for (int l = 0; l < 2; l++) {
        int vv = tid + l * 256;
        int row = vv >> 3, c = (vv & 7) * 4;
        uint4 a = *(const uint4*)(src + (size_t)row * ldw + c);
        *(uint4*)&dst[row * PADW + c] = a;
    }
}

// gmem fp32 [128 x 64] k-contiguous tile -> smem bf16 hi/lo packed
__device__ __forceinline__ void ldcv_tile(
    uint32_t* __restrict__ hi, uint32_t* __restrict__ lo,
    const float* __restrict__ src, int row0, int ld, int tid)
{
#pragma unroll
    for (int l = 0; l < 8; l++) {
        int vv = tid + l * 256;
        int row = vv >> 4, c4 = (vv & 15) * 4;
        float4 a = *(const float4*)(src + (size_t)(row0 + row) * ld + c4);
        uint32_t h0 = pack_hi(a.x, a.y), h1 = pack_hi(a.z, a.w);
        uint32_t l0 = pack_lo(a.x, a.y, h0), l1 = pack_lo(a.z, a.w, h1);
        int kw = row * PADW + (c4 >> 1);
        hi[kw] = h0;  hi[kw + 1] = h1;
        lo[kw] = l0;  lo[kw + 1] = l1;
    }
}

// A = A1 + A2 (out-projection)
__device__ __forceinline__ void ldcv_tile_sum2(
    uint32_t* __restrict__ hi, uint32_t* __restrict__ lo,
    const float* __restrict__ s1, const float* __restrict__ s2,
    int row0, int ld, int tid)
{
#pragma unroll
    for (int l = 0; l < 8; l++) {
        int vv = tid + l * 256;
        int row = vv >> 4, c4 = (vv & 15) * 4;
        size_t off = (size_t)(row0 + row) * ld + c4;
        float4 a = *(const float4*)(s1 + off);
        float4 b = *(const float4*)(s2 + off);
        a.x += b.x; a.y += b.y; a.z += b.z; a.w += b.w;
        uint32_t h0 = pack_hi(a.x, a.y), h1 = pack_hi(a.z, a.w);
        uint32_t l0 = pack_lo(a.x, a.y, h0), l1 = pack_lo(a.z, a.w, h1);
        int kw = row * PADW + (c4 >> 1);
        hi[kw] = h0;  hi[kw + 1] = h1;
        lo[kw] = l0;  lo[kw + 1] = l1;
    }
}

// ============================================================================
// prep kernels: one-time convert of reused operands (bit-identical values)
// ============================================================================
// W[k][n] fp32 -> hi/lo planes [n][kp] (kp packs k even/odd)
__global__ void conv_weights(const float* __restrict__ Wq, const float* __restrict__ Wk,
                             const float* __restrict__ Wv, const float* __restrict__ Wo,
                             uint32_t* __restrict__ Wh, uint32_t* __restrict__ Wl)
{
    const float* W = (blockIdx.y == 0) ? Wq : (blockIdx.y == 1) ? Wk
                   : (blockIdx.y == 2) ? Wv : Wo;
    uint32_t* Hp = Wh + (size_t)blockIdx.y * 512 * 256;
    uint32_t* Lp = Wl + (size_t)blockIdx.y * 512 * 256;
    int idx = blockIdx.x * 256 + threadIdx.x;   // 128 blocks * 256 = 32768
    int n = idx & 511;
    int q = idx >> 9;                            // 0..63
    uint32_t h[4], l[4];
#pragma unroll
    for (int i = 0; i < 4; i++) {
        int k0 = q * 8 + i * 2;
        float a = W[(size_t)k0 * 512 + n];
        float b = W[(size_t)(k0 + 1) * 512 + n];
        h[i] = pack_hi(a, b);
        l[i] = pack_lo(a, b, h[i]);
    }
    *(uint4*)&Hp[(size_t)n * 256 + q * 4] = make_uint4(h[0], h[1], h[2], h[3]);
    *(uint4*)&Lp[(size_t)n * 256 + q * 4] = make_uint4(l[0], l[1], l[2], l[3]);
}

// E[r][d] fp32 -> hi plane [r][kp]
__global__ void conv_E(const float* __restrict__ E, uint32_t* __restrict__ Eh)
{
    int idx = blockIdx.x * 256 + threadIdx.x;    // 64 blocks * 256 = 16384
    int q = idx & 7;                              // 0..7
    int r = idx >> 3;
    float4 a = *(const float4*)(E + (size_t)r * DH_ + q * 8);
    float4 b = *(const float4*)(E + (size_t)r * DH_ + q * 8 + 4);
    uint4 o = make_uint4(pack_hi(a.x, a.y), pack_hi(a.z, a.w),
                         pack_hi(b.x, b.y), pack_hi(b.z, b.w));
    *(uint4*)&Eh[(size_t)r * DHW_ + q * 4] = o;
}

// Vp[b][j][d] fp32 -> per-(b,h) transposed hi/lo planes [d][jp]
__global__ void conv_V(const float* __restrict__ Vp,
                       uint32_t* __restrict__ Vth, uint32_t* __restrict__ Vtl)
{
    int idx = blockIdx.x * 256 + threadIdx.x;    // 1024 blocks * 256 = 262144
    int d = idx & 63;
    int rest = idx >> 6;
    int jq = rest & 255;                          // 0..255 (4 jp each)
    int bh = rest >> 8;                           // 0..15
    int b = bh >> 3, h = bh & 7;
    const float* src = Vp + (size_t)b * S_ * D_ + h * DH_ + d;
    uint32_t hw[4], lw[4];
#pragma unroll
    for (int i = 0; i < 4; i++) {
        int j0 = jq * 8 + i * 2;
        float a = src[(size_t)j0 * D_];
        float c = src[(size_t)(j0 + 1) * D_];
        hw[i] = pack_hi(a, c);
        lw[i] = pack_lo(a, c, hw[i]);
    }
    size_t off = ((size_t)bh * DH_ + d) * (S_ / 2) + jq * 4;
    *(uint4*)&Vth[off] = make_uint4(hw[0], hw[1], hw[2], hw[3]);
    *(uint4*)&Vtl[off] = make_uint4(lw[0], lw[1], lw[2], lw[3]);
}

// ============================================================================
// bf16x3 mainloop (3-pass)
// ============================================================================
__device__ __forceinline__ void tc_nt_mainloop_bf16(
    const uint32_t* __restrict__ Ah, const uint32_t* __restrict__ Al,
    const uint32_t* __restrict__ Bh, const uint32_t* __restrict__ Bl,
    int warp_m, int warp_n, int g, int tg, float acc[4][4][4])
{
#pragma unroll
    for (int ks = 0; ks < 4; ks++) {
        const int base = ks * 8;
        uint32_t bh0[4], bh1[4], bl0[4], bl1[4];
#pragma unroll
        for (int nt = 0; nt < 4; nt++) {
            const int n0 = (warp_n * 32 + nt * 8 + g) * PADW + base + tg;
            bh0[nt] = Bh[n0]; bh1[nt] = Bh[n0 + 4];
            bl0[nt] = Bl[n0]; bl1[nt] = Bl[n0 + 4];
        }
#pragma unroll
        for (int mt = 0; mt < 4; mt++) {
            const int r0 = (warp_m * 64 + mt * 16 + g) * PADW + base + tg;
            const int r1 = r0 + 8 * PADW;
            uint32_t ah0 = Ah[r0], ah1 = Ah[r1], ah2 = Ah[r0 + 4], ah3 = Ah[r1 + 4];
            uint32_t al0 = Al[r0], al1 = Al[r1], al2 = Al[r0 + 4], al3 = Al[r1 + 4];
#pragma unroll
            for (int nt = 0; nt < 4; nt++) {
                mma_bf16(acc[mt][nt], ah0, ah1, ah2, ah3, bh0[nt], bh1[nt]);
                mma_bf16(acc[mt][nt], ah0, ah1, ah2, ah3, bl0[nt], bl1[nt]);
                mma_bf16(acc[mt][nt], al0, al1, al2, al3, bh0[nt], bh1[nt]);
            }
        }
    }
}

// single-pass (hi only)
__device__ __forceinline__ void tc_nt_mainloop_bf16_hi(
    const uint32_t* __restrict__ Ah, const uint32_t* __restrict__ Bh,
    int warp_m, int warp_n, int g, int tg, float acc[4][4][4])
{
#pragma unroll
    for (int ks = 0; ks < 4; ks++) {
        const int base = ks * 8;
        uint32_t bh0[4], bh1[4];
#pragma unroll
        for (int nt = 0; nt < 4; nt++) {
            const int n0 = (warp_n * 32 + nt * 8 + g) * PADW + base + tg;
            bh0[nt] = Bh[n0]; bh1[nt] = Bh[n0 + 4];
        }
#pragma unroll
        for (int mt = 0; mt < 4; mt++) {
            const int r0 = (warp_m * 64 + mt * 16 + g) * PADW + base + tg;
            const int r1 = r0 + 8 * PADW;
            uint32_t ah0 = Ah[r0], ah1 = Ah[r1], ah2 = Ah[r0 + 4], ah3 = Ah[r1 + 4];
#pragma unroll
            for (int nt = 0; nt < 4; nt++)
                mma_bf16(acc[mt][nt], ah0, ah1, ah2, ah3, bh0[nt], bh1[nt]);
        }
    }
}

// AV variant: BM=128 x BN=64.
__device__ __forceinline__ void tc_nt_mainloop_bf16_av(
    const uint32_t* __restrict__ Ah, const uint32_t* __restrict__ Al,
    const uint32_t* __restrict__ Bh, const uint32_t* __restrict__ Bl,
    int warp_m, int warp_n, int g, int tg, float acc[2][4][4])
{
#pragma unroll
    for (int ks = 0; ks < 4; ks++) {
        const int base = ks * 8;
        uint32_t bh0[4], bh1[4], bl0[4], bl1[4];
#pragma unroll
        for (int nt = 0; nt < 4; nt++) {
            const int n0 = (warp_n * 32 + nt * 8 + g) * PADW + base + tg;
            bh0[nt] = Bh[n0]; bh1[nt] = Bh[n0 + 4];
            bl0[nt] = Bl[n0]; bl1[nt] = Bl[n0 + 4];
        }
#pragma unroll
        for (int mt = 0; mt < 2; mt++) {
            const int r0 = (warp_m * 32 + mt * 16 + g) * PADW + base + tg;
            const int r1 = r0 + 8 * PADW;
            uint32_t ah0 = Ah[r0], ah1 = Ah[r1], ah2 = Ah[r0 + 4], ah3 = Ah[r1 + 4];
            uint32_t al0 = Al[r0], al1 = Al[r1], al2 = Al[r0 + 4], al3 = Al[r1 + 4];
#pragma unroll
            for (int nt = 0; nt < 4; nt++) {
                mma_bf16(acc[mt][nt], ah0, ah1, ah2, ah3, bh0[nt], bh1[nt]);
                mma_bf16(acc[mt][nt], ah0, ah1, ah2, ah3, bl0[nt], bl1[nt]);
                mma_bf16(acc[mt][nt], al0, al1, al2, al3, bh0[nt], bh1[nt]);
            }
        }
    }
}

// ============================================================================
// QE GEMM (NT, single-pass bf16): zero conversions (Q and E pre-packed).
// ============================================================================
__global__ __launch_bounds__(256) void gemm_qe(
    const uint32_t* __restrict__ Qh, const uint32_t* __restrict__ Eh,
    __half* __restrict__ QE)
{
    if (blockIdx.x + blockIdx.y < 15) return;   // never-read tiles
    const int bh = blockIdx.z;
    const uint32_t* A = Qh + (size_t)(bh >> 3) * S_ * DW_ + (bh & 7) * DHW_;
    const int bm = blockIdx.y * 128;
    const int bn = blockIdx.x * 128;
    const int tid = threadIdx.x;
    const int lane = tid & 31, wid = tid >> 5;
    const int warp_m = wid & 1, warp_n = wid >> 1;
    const int g = lane >> 2, tg = lane & 3;

    extern __shared__ uint32_t smw[];
    uint32_t* Ah = smw;
    uint32_t* Bh = smw + TILE_W;

    ld_tile_pk(Ah, A, bm, DW_, tid);
    ld_tile_pk(Bh, Eh, bn, DHW_, tid);
    __syncthreads();

    float acc[4][4][4];
#pragma unroll
    for (int a = 0; a < 4; a++)
#pragma unroll
        for (int b = 0; b < 4; b++)
#pragma unroll
            for (int c = 0; c < 4; c++) acc[a][b][c] = 0.f;

    tc_nt_mainloop_bf16_hi(Ah, Bh, warp_m, warp_n, g, tg, acc);

    __half* Cb = QE + (size_t)bh * S_ * MM_;
#pragma unroll
    for (int mt = 0; mt < 4; mt++) {
        const int i0 = bm + warp_m * 64 + mt * 16 + g;
#pragma unroll
        for (int nt = 0; nt < 4; nt++) {
            const int j0 = bn + warp_n * 32 + nt * 8 + 2 * tg;
            *(__half2*)(Cb + (size_t)i0 * MM_ + j0) =
                __floats2half2_rn(acc[mt][nt][0], acc[mt][nt][1]);
            *(__half2*)(Cb + (size_t)(i0 + 8) * MM_ + j0) =
                __floats2half2_rn(acc[mt][nt][2], acc[mt][nt][3]);
        }
    }
}

// ============================================================================
// Logits (NT, causal, bf16x3), split epilogue (R16 winner, unchanged).
// ============================================================================
__global__ __launch_bounds__(256) void logits_kernel(
    const uint32_t* __restrict__ Qh, const uint32_t* __restrict__ Ql,
    const uint32_t* __restrict__ Kh, const uint32_t* __restrict__ Kl,
    const __half* __restrict__ QE, float* __restrict__ attn)
{
    const int bm = blockIdx.y * 128;
    const int bn = blockIdx.x * 128;
    if (bn > bm + 127) return;
    const int bh = blockIdx.z;
    const size_t hoff = (size_t)(bh >> 3) * S_ * DW_ + (bh & 7) * DHW_;
    const int tid = threadIdx.x;
    const int lane = tid & 31, wid = tid >> 5;
    const int warp_m = wid & 1, warp_n = wid >> 1;
    const int g = lane >> 2, tg = lane & 3;

    extern __shared__ uint32_t smw[];
    uint32_t* Ah = smw;
    uint32_t* Al = smw + TILE_W;
    uint32_t* Bh = smw + 2 * TILE_W;
    uint32_t* Bl = smw + 3 * TILE_W;

    ld_tile_pk(Ah, Qh + hoff, bm, DW_, tid);
    ld_tile_pk(Al, Ql + hoff, bm, DW_, tid);
    ld_tile_pk(Bh, Kh + hoff, bn, DW_, tid);
    ld_tile_pk(Bl, Kl + hoff, bn, DW_, tid);
    __syncthreads();

    float acc[4][4][4];
#pragma unroll
    for (int a = 0; a < 4; a++)
#pragma unroll
        for (int b = 0; b < 4; b++)
#pragma unroll
            for (int c = 0; c < 4; c++) acc[a][b][c] = 0.f;

    tc_nt_mainloop_bf16(Ah, Al, Bh, Bl, warp_m, warp_n, g, tg, acc);

    const __half* QEr = QE + (size_t)bh * S_ * MM_;
    float* Cb = attn + (size_t)bh * S_ * S_;

    if (bn < bm) {
#pragma unroll
        for (int mt = 0; mt < 4; mt++) {
            const int ia = bm + warp_m * 64 + mt * 16 + g;
            const int ib = ia + 8;
            const __half* qa = QEr + (size_t)ia * MM_ + (MM_ - 1 - ia);
            const __half* qb = QEr + (size_t)ib * MM_ + (MM_ - 1 - ib);
            float* ca = Cb + (size_t)ia * S_;
            float* cbp = Cb + (size_t)ib * S_;
#pragma unroll
            for (int nt = 0; nt < 4; nt++) {
                const int j0 = bn + warp_n * 32 + nt * 8 + 2 * tg;
                float2 oa, ob;
                oa.x = (acc[mt][nt][0] + __half2float(qa[j0]))     * 0.125f;
                oa.y = (acc[mt][nt][1] + __half2float(qa[j0 + 1])) * 0.125f;
                ob.x = (acc[mt][nt][2] + __half2float(qb[j0]))     * 0.125f;
                ob.y = (acc[mt][nt][3] + __half2float(qb[j0 + 1])) * 0.125f;
                *(float2*)(ca + j0)  = oa;
                *(float2*)(cbp + j0) = ob;
            }
        }
    } else {
#pragma unroll
        for (int mt = 0; mt < 4; mt++) {
            const int ia = bm + warp_m * 64 + mt * 16 + g;
            const int ib = ia + 8;
#pragma unroll
            for (int nt = 0; nt < 4; nt++) {
                const int j0 = bn + warp_n * 32 + nt * 8 + 2 * tg;
                const int j1 = j0 + 1;
                if (j0 <= ia)
                    Cb[(size_t)ia * S_ + j0] =
                        (acc[mt][nt][0] + __half2float(QEr[(size_t)ia * MM_ + (j0 - ia + MM_ - 1)])) * 0.125f;
                if (j1 <= ia)
                    Cb[(size_t)ia * S_ + j1] =
                        (acc[mt][nt][1] + __half2float(QEr[(size_t)ia * MM_ + (j1 - ia + MM_ - 1)])) * 0.125f;
                if (j0 <= ib)
                    Cb[(size_t)ib * S_ + j0] =
                        (acc[mt][nt][2] + __half2float(QEr[(size_t)ib * MM_ + (j0 - ib + MM_ - 1)])) * 0.125f;
                if (j1 <= ib)
                    Cb[(size_t)ib * S_ + j1] =
                        (acc[mt][nt][3] + __half2float(QEr[(size_t)ib * MM_ + (j1 - ib + MM_ - 1)])) * 0.125f;
            }
        }
    }
}

// ============================================================================
// Fused QKV projection (NN, bf16x3): W from pre-packed planes; Q,K written as
// packed bf16 hi/lo planes; V fp32.
// ============================================================================
__global__ __launch_bounds__(256) void proj_qkv(
    const float* __restrict__ q,  const float* __restrict__ k,
    const float* __restrict__ v,
    const uint32_t* __restrict__ Wh, const uint32_t* __restrict__ Wl,
    const float* __restrict__ bq, const float* __restrict__ bk,
    const float* __restrict__ bv,
    uint32_t* __restrict__ Qh, uint32_t* __restrict__ Ql,
    uint32_t* __restrict__ Kh, uint32_t* __restrict__ Kl,
    float* __restrict__ Vp)
{
    const float *A, *bias;
    uint32_t *Ch = nullptr, *Cl = nullptr;
    if (blockIdx.z == 0)      { A = q; bias = bq; Ch = Qh; Cl = Ql; }
    else if (blockIdx.z == 1) { A = k; bias = bk; Ch = Kh; Cl = Kl; }
    else                      { A = v; bias = bv; }
    const uint32_t* WhP = Wh + (size_t)blockIdx.z * 512 * 256;
    const uint32_t* WlP = Wl + (size_t)blockIdx.z * 512 * 256;

    const int bm = blockIdx.y * 128;
    const int bn = blockIdx.x * 128;
    const int tid = threadIdx.x;
    const int lane = tid & 31, wid = tid >> 5;
    const int warp_m = wid & 1, warp_n = wid >> 1;
    const int g = lane >> 2, tg = lane & 3;

    extern __shared__ uint32_t smw[];
    uint32_t* Ah = smw;
    uint32_t* Al = smw + TILE_W;
    uint32_t* Bh = smw + 2 * TILE_W;
    uint32_t* Bl = smw + 3 * TILE_W;

    float acc[4][4][4];
#pragma unroll
    for (int a = 0; a < 4; a++)
#pragma unroll
        for (int b = 0; b < 4; b++)
#pragma unroll
            for (int c = 0; c < 4; c++) acc[a][b][c] = 0.f;

    for (int k0 = 0; k0 < D_; k0 += 64) {
        ldcv_tile(Ah, Al, A + k0, bm, D_, tid);
        ld_tile_pk(Bh, WhP + (k0 >> 1), bn, 256, tid);
        ld_tile_pk(Bl, WlP + (k0 >> 1), bn, 256, tid);
        __syncthreads();
        tc_nt_mainloop_bf16(Ah, Al, Bh, Bl, warp_m, warp_n, g, tg, acc);
        __syncthreads();
    }

#pragma unroll
    for (int mt = 0; mt < 4; mt++) {
        const int i0 = bm + warp_m * 64 + mt * 16 + g;
#pragma unroll
        for (int nt = 0; nt < 4; nt++) {
            const int j0 = bn + warp_n * 32 + nt * 8 + 2 * tg;
            float b0 = bias[j0], b1 = bias[j0 + 1];
            float x0 = acc[mt][nt][0] + b0, x1 = acc[mt][nt][1] + b1;
            float y0 = acc[mt][nt][2] + b0, y1 = acc[mt][nt][3] + b1;
            if (blockIdx.z == 2) {
                *(float2*)(Vp + (size_t)i0 * D_ + j0)       = make_float2(x0, x1);
                *(float2*)(Vp + (size_t)(i0 + 8) * D_ + j0) = make_float2(y0, y1);
            } else {
                uint32_t h0 = pack_hi(x0, x1), l0 = pack_lo(x0, x1, h0);
                uint32_t h1 = pack_hi(y0, y1), l1 = pack_lo(y0, y1, h1);
                size_t w0 = (size_t)i0 * DW_ + (j0 >> 1);
                size_t w1 = (size_t)(i0 + 8) * DW_ + (j0 >> 1);
                Ch[w0] = h0;  Cl[w0] = l0;
                Ch[w1] = h1;  Cl[w1] = l1;
            }
        }
    }
}

// ============================================================================
// Out projection (NN, bf16x3) with summed A; Wo from pre-packed planes.
// ============================================================================
__global__ __launch_bounds__(256) void sgemm_sum2_nn_bias(
    const float* __restrict__ A1, const float* __restrict__ A2,
    const uint32_t* __restrict__ Wh, const uint32_t* __restrict__ Wl,
    const float* __restrict__ bias, float* __restrict__ C)
{
    const uint32_t* WhP = Wh + (size_t)3 * 512 * 256;
    const uint32_t* WlP = Wl + (size_t)3 * 512 * 256;
    const int bm = blockIdx.y * 128;
    const int bn = blockIdx.x * 128;
    const int tid = threadIdx.x;
    const int lane = tid & 31, wid = tid >> 5;
    const int warp_m = wid & 1, warp_n = wid >> 1;
    const int g = lane >> 2, tg = lane & 3;

    extern __shared__ uint32_t smw[];
    uint32_t* Ah = smw;
    uint32_t* Al = smw + TILE_W;
    uint32_t* Bh = smw + 2 * TILE_W;
    uint32_t* Bl = smw + 3 * TILE_W;

    float acc[4][4][4];
#pragma unroll
    for (int a = 0; a < 4; a++)
#pragma unroll
        for (int b = 0; b < 4; b++)
#pragma unroll
            for (int c = 0; c < 4; c++) acc[a][b][c] = 0.f;

    for (int k0 = 0; k0 < D_; k0 += 64) {
        ldcv_tile_sum2(Ah, Al, A1 + k0, A2 + k0, bm, D_, tid);
        ld_tile_pk(Bh, WhP + (k0 >> 1), bn, 256, tid);
        ld_tile_pk(Bl, WlP + (k0 >> 1), bn, 256, tid);
        __syncthreads();
        tc_nt_mainloop_bf16(Ah, Al, Bh, Bl, warp_m, warp_n, g, tg, acc);
        __syncthreads();
    }

#pragma unroll
    for (int mt = 0; mt < 4; mt++) {
        const int i0 = bm + warp_m * 64 + mt * 16 + g;
#pragma unroll
        for (int nt = 0; nt < 4; nt++) {
            const int j0 = bn + warp_n * 32 + nt * 8 + 2 * tg;
            float b0 = bias[j0], b1 = bias[j0 + 1];
            *(float2*)(C + (size_t)i0 * D_ + j0) =
                make_float2(acc[mt][nt][0] + b0, acc[mt][nt][1] + b1);
            *(float2*)(C + (size_t)(i0 + 8) * D_ + j0) =
                make_float2(acc[mt][nt][2] + b0, acc[mt][nt][3] + b1);
        }
    }
}

// ============================================================================
// Causal row softmax (full-row stores incl. exact-zero tail).
// ============================================================================
__global__ void softmax_causal(float* __restrict__ attn)
{
    const int row = blockIdx.x;
    const int i   = row & (S_ - 1);
    float* p = attn + (size_t)row * S_;
    const int tid = threadIdx.x;

    float r[8];
    float mx = -1e30f;
#pragma unroll
    for (int l = 0; l < 8; l++) {
        int j = tid + (l << 8);
        r[l] = (j <= i) ? p[j] : -1e30f;
        mx = fmaxf(mx, r[l]);
    }
#pragma unroll
    for (int o = 16; o > 0; o >>= 1)
        mx = fmaxf(mx, __shfl_xor_sync(0xffffffffu, mx, o));
    __shared__ float smx[8];
    __shared__ float ssum[8];
    if ((tid & 31) == 0) smx[tid >> 5] = mx;
    __syncthreads();
#pragma unroll
    for (int w = 0; w < 8; w++) mx = fmaxf(mx, smx[w]);

    float sum = 0.f;
#pragma unroll
    for (int l = 0; l < 8; l++) {
        int j = tid + (l << 8);
        r[l] = (j <= i) ? __expf(r[l] - mx) : 0.f;
        sum += r[l];
    }
#pragma unroll
    for (int o = 16; o > 0; o >>= 1)
        sum += __shfl_xor_sync(0xffffffffu, sum, o);
    if ((tid & 31) == 0) ssum[tid >> 5] = sum;
    __syncthreads();
    float tot = 0.f;
#pragma unroll
    for (int w = 0; w < 8; w++) tot += ssum[w];
    const float inv = 1.f / tot;

#pragma unroll
    for (int l = 0; l < 8; l++) p[tid + (l << 8)] = r[l] * inv;
}

// ============================================================================
// AV GEMM (NN, bf16x3): causal, split-K x2, heavy first; V from packed planes.
// ============================================================================
__global__ __launch_bounds__(256) void av_kernel(
    const float* __restrict__ attn,
    const uint32_t* __restrict__ Vth, const uint32_t* __restrict__ Vtl,
    float* __restrict__ O0, float* __restrict__ O1)
{
    const int bh = blockIdx.z;
    const int b = bh >> 3, h = bh & 7;
    const int bm = (15 - blockIdx.y) * 128;
    const int kend = bm + 128;
    const int half = kend >> 1;
    const int kbeg = blockIdx.x * half;
    const int kfin = kbeg + half;
    float* Ot = blockIdx.x ? O1 : O0;

    const float* Ar = attn + (size_t)bh * S_ * S_;
    const uint32_t* Vh = Vth + (size_t)bh * DH_ * (S_ / 2);
    const uint32_t* Vl = Vtl + (size_t)bh * DH_ * (S_ / 2);
    const int tid = threadIdx.x;
    const int lane = tid & 31, wid = tid >> 5;
    const int warp_m = wid & 3, warp_n = wid >> 2;
    const int g = lane >> 2, tg = lane & 3;

    extern __shared__ uint32_t smw[];
    uint32_t* Ah = smw;
    uint32_t* Al = smw + TILE_W;
    uint32_t* Bh = smw + 2 * TILE_W;
    uint32_t* Bl = smw + 2 * TILE_W + TILE_W64;

    float acc[2][4][4];
#pragma unroll
    for (int a = 0; a < 2; a++)
#pragma unroll
        for (int c = 0; c < 4; c++)
#pragma unroll
            for (int d = 0; d < 4; d++) acc[a][c][d] = 0.f;

    for (int k0 = kbeg; k0 < kfin; k0 += 64) {
        ldcv_tile(Ah, Al, Ar + k0, bm, S_, tid);
        ld_tile_pk64(Bh, Vh + (k0 >> 1), S_ / 2, tid);
        ld_tile_pk64(Bl, Vl + (k0 >> 1), S_ / 2, tid);
        __syncthreads();
        tc_nt_mainloop_bf16_av(Ah, Al, Bh, Bl, warp_m, warp_n, g, tg, acc);
        __syncthreads();
    }

    float* Ob = Ot + (size_t)b * S_ * D_ + h * DH_;
#pragma unroll
    for (int mt = 0; mt < 2; mt++) {
        const int i0 = bm + warp_m * 32 + mt * 16 + g;
#pragma unroll
        for (int nt = 0; nt < 4; nt++) {
            const int j0 = warp_n * 32 + nt * 8 + 2 * tg;
            *(float2*)(Ob + (size_t)i0 * D_ + j0) =
                make_float2(acc[mt][nt][0], acc[mt][nt][1]);
            *(float2*)(Ob + (size_t)(i0 + 8) * D_ + j0) =
                make_float2(acc[mt][nt][2], acc[mt][nt][3]);
        }
    }
}

// ============================================================================
// launch
// ============================================================================
extern "C" void kernel_launch(void* const* d_in, const int* in_sizes, int n_in,
                              void* d_out, int out_size)
{
    const float* v  = (const float*)d_in[0];
    const float* k  = (const float*)d_in[1];
    const float* q  = (const float*)d_in[2];
    // d_in[3] = mask (implemented analytically)
    const float* Wq = (const float*)d_in[4];
    const float* bq = (const float*)d_in[5];
    const float* Wk = (const float*)d_in[6];
    const float* bk = (const float*)d_in[7];
    const float* Wv = (const float*)d_in[8];
    const float* bv = (const float*)d_in[9];
    const float* Wo = (const float*)d_in[10];
    const float* bo = (const float*)d_in[11];
    const float* E  = (const float*)d_in[12];

    float* out  = (float*)d_out;                       // (B,S,D)
    float* attn = (float*)d_out + (size_t)B_*S_*D_;    // (B,H,S,S)

    uint32_t *Qh, *Ql, *Kh, *Kl, *Wh, *Wl, *Eh, *Vth, *Vtl;
    float *Vp, *Tmp, *Tmp2;
    __half* QE;
    cudaGetSymbolAddress((void**)&Qh,   g_Qh);
    cudaGetSymbolAddress((void**)&Ql,   g_Ql);
    cudaGetSymbolAddress((void**)&Kh,   g_Kh);
    cudaGetSymbolAddress((void**)&Kl,   g_Kl);
    cudaGetSymbolAddress((void**)&Vp,   g_Vp);
    cudaGetSymbolAddress((void**)&Tmp,  g_tmp);
    cudaGetSymbolAddress((void**)&Tmp2, g_tmp2);
    cudaGetSymbolAddress((void**)&QE,   g_QE);
    cudaGetSymbolAddress((void**)&Wh,   g_Wh);
    cudaGetSymbolAddress((void**)&Wl,   g_Wl);
    cudaGetSymbolAddress((void**)&Eh,   g_Eh);
    cudaGetSymbolAddress((void**)&Vth,  g_Vth);
    cudaGetSymbolAddress((void**)&Vtl,  g_Vtl);

    static int attr_done = 0;
    if (!attr_done) {
        cudaFuncSetAttribute(logits_kernel,      cudaFuncAttributeMaxDynamicSharedMemorySize, SMEM_TC);
        cudaFuncSetAttribute(proj_qkv,           cudaFuncAttributeMaxDynamicSharedMemorySize, SMEM_TC);
        cudaFuncSetAttribute(sgemm_sum2_nn_bias, cudaFuncAttributeMaxDynamicSharedMemorySize, SMEM_TC);
        cudaFuncSetAttribute(av_kernel,          cudaFuncAttributeMaxDynamicSharedMemorySize, SMEM_AV);
        attr_done = 1;
    }

    // one-time operand conversion (graph-captured each replay; cheap)
    conv_weights<<<dim3(128, 4), 256>>>(Wq, Wk, Wv, Wo, Wh, Wl);
    conv_E<<<64, 256>>>(E, Eh);

    dim3 gProj(D_ / 128, (B_*S_) / 128, 3);  // (4, 32, 3)
    proj_qkv<<<gProj, 256, SMEM_TC>>>(q, k, v, Wh, Wl, bq, bk, bv,
                                      Qh, Ql, Kh, Kl, Vp);

    conv_V<<<1024, 256>>>(Vp, Vth, Vtl);

    dim3 gQE(MM_ / 128, S_ / 128, BH_);      // triangular early-exit
    gemm_qe<<<gQE, 256, SMEM_QE>>>(Qh, Eh, QE);

    dim3 gLg(S_ / 128, S_ / 128, BH_);       // upper tiles early-exit
    logits_kernel<<<gLg, 256, SMEM_TC>>>(Qh, Ql, Kh, Kl, QE, attn);

    softmax_causal<<<BH_ * S_, 256>>>(attn);

    dim3 gAV(2, S_ / 128, BH_);              // split-K x2
    av_kernel<<<gAV, 256, SMEM_AV>>>(attn, Vth, Vtl, Tmp, Tmp2);

    dim3 gOut(D_ / 128, (B_*S_) / 128);
    sgemm_sum2_nn_bias<<<gOut, 256, SMEM_TC>>>(Tmp, Tmp2, Wh, Wl, bo, out);
}